// round 5
// baseline (speedup 1.0000x reference)
#include <cuda_runtime.h>
#include <cuda_bf16.h>
#include <cstddef>

#define B_ 2
#define L_ 1920
#define D_ 512
#define H_ 8
#define DH_ 64
#define BH_ (B_*H_)
#define NT_ 30
#define OUT_ELEMS (B_*L_*D_)
#define NSPLIT 4
#define SPLITW 480

typedef unsigned long long u64;

__device__ __forceinline__ u64 pack2(float lo, float hi) {
    u64 d; asm("mov.b64 %0,{%1,%2};" : "=l"(d) : "f"(lo), "f"(hi)); return d;
}
__device__ __forceinline__ u64 dup2(float v) { return pack2(v, v); }
__device__ __forceinline__ void unpack2(u64 v, float& lo, float& hi) {
    asm("mov.b64 {%0,%1},%2;" : "=f"(lo), "=f"(hi) : "l"(v));
}
#define FMA2(acc, a, b) \
    asm("fma.rn.f32x2 %0,%1,%2,%0;" : "+l"(acc) : "l"(a), "l"(b))

// Scratch (device globals; no cudaMalloc allowed)
__device__ float g_qp[B_*L_*D_];
__device__ float g_kp[B_*L_*D_];
__device__ float g_vp[B_*L_*D_];
__device__ float g_op[NSPLIT * BH_*L_*DH_];
__device__ float2 g_stats[BH_*NT_*L_];
__device__ float g_M[BH_*L_];
__device__ float g_I[BH_*L_];

// ---------------------------------------------------------------------------
// QKV projection, f32x2 microkernel. Tile 64x64, 256 thr, micro 4x4.
// ---------------------------------------------------------------------------
__global__ __launch_bounds__(256)
void qkv_proj_kernel(const float* __restrict__ q, const float* __restrict__ k,
                     const float* __restrict__ v,
                     const float* __restrict__ Wq, const float* __restrict__ Wk,
                     const float* __restrict__ Wv,
                     const float* __restrict__ bq, const float* __restrict__ bk,
                     const float* __restrict__ bv)
{
    const float* A; const float* W; const float* bias; float* C;
    int z = blockIdx.z;
    if (z == 0)      { A = q; W = Wq; bias = bq; C = g_qp; }
    else if (z == 1) { A = k; W = Wk; bias = bk; C = g_kp; }
    else             { A = v; W = Wv; bias = bv; C = g_vp; }

    __shared__ u64 As2[16][66];   // duplicated (v,v)
    __shared__ u64 Bs2[16][34];   // natural pairs
    int tid = threadIdx.x;
    int tx = tid & 15, ty = tid >> 4;
    int m0 = blockIdx.y * 64, n0 = blockIdx.x * 64;
    u64 acc[4][2] = {};

    int mA = tid >> 2, gA = tid & 3;
    int kB = tid >> 4, gB = tid & 15;

    for (int k0 = 0; k0 < 512; k0 += 16) {
        float4 av = *(const float4*)(A + (size_t)(m0 + mA) * 512 + k0 + gA * 4);
        As2[gA*4+0][mA] = dup2(av.x); As2[gA*4+1][mA] = dup2(av.y);
        As2[gA*4+2][mA] = dup2(av.z); As2[gA*4+3][mA] = dup2(av.w);
        float4 wv = *(const float4*)(W + (size_t)(k0 + kB) * 512 + n0 + gB * 4);
        Bs2[kB][gB*2+0] = pack2(wv.x, wv.y);
        Bs2[kB][gB*2+1] = pack2(wv.z, wv.w);
        __syncthreads();
        #pragma unroll
        for (int kk = 0; kk < 16; kk++) {
            u64 a[4], b[2];
            #pragma unroll
            for (int i = 0; i < 4; i++) a[i] = As2[kk][ty*4 + i];
            b[0] = Bs2[kk][tx*2 + 0];
            b[1] = Bs2[kk][tx*2 + 1];
            #pragma unroll
            for (int i = 0; i < 4; i++) {
                FMA2(acc[i][0], a[i], b[0]);
                FMA2(acc[i][1], a[i], b[1]);
            }
        }
        __syncthreads();
    }
    #pragma unroll
    for (int i = 0; i < 4; i++) {
        float4 o;
        unpack2(acc[i][0], o.x, o.y);
        unpack2(acc[i][1], o.z, o.w);
        o.x += bias[n0 + tx*4 + 0]; o.y += bias[n0 + tx*4 + 1];
        o.z += bias[n0 + tx*4 + 2]; o.w += bias[n0 + tx*4 + 3];
        *(float4*)(C + (size_t)(m0 + ty*4 + i) * 512 + n0 + tx*4) = o;
    }
}

// ---------------------------------------------------------------------------
// Scores, f32x2. Tile 128q x 64k, 256 thr, micro 8x4 (2 col-pairs).
// logits = (Q.K + Q.E[rel]) * 0.125 ; also per-(row, 64-k-tile) stats.
// Triangular grid over (qt128, kt64): kt in [0, 2qt+2), 240 blocks.
// ---------------------------------------------------------------------------
__global__ __launch_bounds__(256)
void scores_kernel(const float* __restrict__ E, float* __restrict__ attn)
{
    int idx = blockIdx.x;
    int qt = (int)((sqrtf(4.f * idx + 1.f) - 1.f) * 0.5f);
    while ((qt + 1) * (qt + 2) <= idx) qt++;
    while (qt * (qt + 1) > idx) qt--;
    int kt = idx - qt * (qt + 1);         // in [0, 2qt+2)

    int bh = blockIdx.y;
    int b = bh >> 3, h = bh & 7;
    int q0 = qt * 128, k0 = kt * 64;

    __shared__ u64  Qs2[16][130];         // duplicated
    __shared__ float Ksf[16][68];         // scalar view; pairs at even cols
    __shared__ float Esf[16][196];

    int tid = threadIdx.x;
    int tx = tid & 15, ty = tid >> 4;
    u64 acc[8][2] = {};

    const float* qbase = g_qp + (size_t)b * L_ * 512 + h * 64;
    const float* kbase = g_kp + (size_t)b * L_ * 512 + h * 64;
    // Es[ro] holds E row (rbase + ro + 1), ro = kc - qr + 127 in [0,191]
    // identity: rbase + ro = rel + 1919  =>  rbase = k0 - q0 + 1792
    int rbase = k0 - q0 - 127 + 1919;

    int mQ = tid >> 1, gQ = tid & 1;      // Q: row mQ, 8-dim half gQ
    int kB = tid >> 2, gB = tid & 3;      // K: row kB, float4 gB

    for (int dc = 0; dc < 4; dc++) {
        int d0 = dc * 16;
        {
            float4 qa = *(const float4*)(qbase + (size_t)(q0 + mQ) * 512 + d0 + gQ*8);
            float4 qb = *(const float4*)(qbase + (size_t)(q0 + mQ) * 512 + d0 + gQ*8 + 4);
            Qs2[gQ*8+0][mQ] = dup2(qa.x); Qs2[gQ*8+1][mQ] = dup2(qa.y);
            Qs2[gQ*8+2][mQ] = dup2(qa.z); Qs2[gQ*8+3][mQ] = dup2(qa.w);
            Qs2[gQ*8+4][mQ] = dup2(qb.x); Qs2[gQ*8+5][mQ] = dup2(qb.y);
            Qs2[gQ*8+6][mQ] = dup2(qb.z); Qs2[gQ*8+7][mQ] = dup2(qb.w);
            float4 kv = *(const float4*)(kbase + (size_t)(k0 + kB) * 512 + d0 + gB*4);
            Ksf[gB*4+0][kB] = kv.x; Ksf[gB*4+1][kB] = kv.y;
            Ksf[gB*4+2][kB] = kv.z; Ksf[gB*4+3][kB] = kv.w;
        }
        #pragma unroll
        for (int r = 0; r < 3; r++) {
            int i2 = tid + r * 256;           // 0..767
            int ro = i2 >> 2, g = i2 & 3;     // ro 0..191
            int rr = rbase + ro;
            float4 ev = make_float4(0.f, 0.f, 0.f, 0.f);
            if (rr >= 0 && rr < L_)
                ev = *(const float4*)(E + (size_t)(rr + 1) * 512 + h * 64 + d0 + g*4);
            Esf[g*4+0][ro] = ev.x; Esf[g*4+1][ro] = ev.y;
            Esf[g*4+2][ro] = ev.z; Esf[g*4+3][ro] = ev.w;
        }
        __syncthreads();
        int tbase = 4*tx - 8*ty + 127;        // col - row + 127 at (i=0,jp=0)
        #pragma unroll
        for (int dd = 0; dd < 16; dd++) {
            u64 a[8], kv[2];
            #pragma unroll
            for (int i = 0; i < 8; i++) a[i] = Qs2[dd][ty*8 + i];
            kv[0] = *(const u64*)&Ksf[dd][tx*4 + 0];
            kv[1] = *(const u64*)&Ksf[dd][tx*4 + 2];
            float e[11];
            #pragma unroll
            for (int t = 0; t < 11; t++) e[t] = Esf[dd][tbase - 7 + t];
            u64 evp[10];
            #pragma unroll
            for (int j = 0; j < 10; j++) evp[j] = pack2(e[j], e[j+1]);
            #pragma unroll
            for (int i = 0; i < 8; i++) {
                FMA2(acc[i][0], a[i], kv[0]);
                FMA2(acc[i][0], a[i], evp[7 - i]);      // u = -i
                FMA2(acc[i][1], a[i], kv[1]);
                FMA2(acc[i][1], a[i], evp[9 - i]);      // u = 2 - i
            }
        }
        __syncthreads();
    }

    bool partial = (k0 + 63 > q0);
    #pragma unroll
    for (int i = 0; i < 8; i++) {
        int row = ty * 8 + i;
        float v[4];
        unpack2(acc[i][0], v[0], v[1]);
        unpack2(acc[i][1], v[2], v[3]);
        #pragma unroll
        for (int j = 0; j < 4; j++) v[j] *= 0.125f;
        *(float4*)(attn + ((size_t)bh * L_ + q0 + row) * L_ + k0 + tx*4) =
            make_float4(v[0], v[1], v[2], v[3]);

        int qrow = q0 + row;
        float m = -1e30f;
        #pragma unroll
        for (int j = 0; j < 4; j++) {
            bool valid = !partial || (k0 + tx*4 + j <= qrow);
            if (valid) m = fmaxf(m, v[j]);
        }
        #pragma unroll
        for (int off = 8; off > 0; off >>= 1)
            m = fmaxf(m, __shfl_xor_sync(0xffffffffu, m, off, 16));
        float s = 0.f;
        #pragma unroll
        for (int j = 0; j < 4; j++) {
            bool valid = !partial || (k0 + tx*4 + j <= qrow);
            if (valid) s += __expf(v[j] - m);
        }
        #pragma unroll
        for (int off = 8; off > 0; off >>= 1)
            s += __shfl_xor_sync(0xffffffffu, s, off, 16);
        if (tx == 0)
            g_stats[((size_t)bh * NT_ + kt) * L_ + qrow] = make_float2(m, s);
    }
}

// ---------------------------------------------------------------------------
// Combine per-tile stats into per-row (max, 1/sum).
// ---------------------------------------------------------------------------
__global__ __launch_bounds__(256)
void statcomb_kernel()
{
    int p = blockIdx.x * 256 + threadIdx.x;
    if (p >= BH_ * L_) return;
    int bh = p / L_, q = p - bh * L_;
    int nt = q / 64 + 1;

    const float2* st = g_stats + (size_t)bh * NT_ * L_ + q;
    float M = -1e30f;
    for (int t = 0; t < nt; t++) M = fmaxf(M, st[(size_t)t * L_].x);
    float S = 0.f;
    for (int t = 0; t < nt; t++) {
        float2 v = st[(size_t)t * L_];
        S += v.y * __expf(v.x - M);
    }
    g_M[p] = M;
    g_I[p] = 1.f / S;
}

// ---------------------------------------------------------------------------
// Fused normalize + AV (split-K) + zerofill of this split's k>q columns.
// ---------------------------------------------------------------------------
__global__ __launch_bounds__(256)
void av_kernel(float* __restrict__ attn)
{
    int qt = blockIdx.x;
    int bh = blockIdx.y;
    int s  = blockIdx.z;
    int b = bh >> 3, h = bh & 7;
    int q0 = qt * 64;
    int tid = threadIdx.x;

    int kbeg = s * SPLITW;
    int kend = min(q0 + 64, kbeg + SPLITW);

    float* arow = attn + ((size_t)bh * L_ + q0) * L_;

    if (kbeg < kend) {
        __shared__ u64 As2[16][66];
        __shared__ u64 Bs2[16][34];
        __shared__ float sM[64];
        __shared__ float sI[64];
        int tx = tid & 15, ty = tid >> 4;
        u64 acc[4][2] = {};

        if (tid < 64) {
            sM[tid] = g_M[(size_t)bh * L_ + q0 + tid];
            sI[tid] = g_I[(size_t)bh * L_ + q0 + tid];
        }
        __syncthreads();

        const float* vbase = g_vp + (size_t)b * L_ * 512 + h * 64;
        int mA = tid >> 2, gA = tid & 3;
        int kB = tid >> 4, gB = tid & 15;
        float Mr = sM[mA], Ir = sI[mA];
        int qrow = q0 + mA;

        for (int k0 = kbeg; k0 < kend; k0 += 16) {
            float4 xv = *(float4*)(arow + (size_t)mA * L_ + k0 + gA * 4);
            int kb = k0 + gA * 4;
            float4 p;
            p.x = (kb + 0 <= qrow) ? __expf(xv.x - Mr) * Ir : 0.f;
            p.y = (kb + 1 <= qrow) ? __expf(xv.y - Mr) * Ir : 0.f;
            p.z = (kb + 2 <= qrow) ? __expf(xv.z - Mr) * Ir : 0.f;
            p.w = (kb + 3 <= qrow) ? __expf(xv.w - Mr) * Ir : 0.f;
            *(float4*)(arow + (size_t)mA * L_ + k0 + gA * 4) = p;
            As2[gA*4+0][mA] = dup2(p.x); As2[gA*4+1][mA] = dup2(p.y);
            As2[gA*4+2][mA] = dup2(p.z); As2[gA*4+3][mA] = dup2(p.w);
            float4 vv = *(const float4*)(vbase + (size_t)(k0 + kB) * 512 + gB * 4);
            Bs2[kB][gB*2+0] = pack2(vv.x, vv.y);
            Bs2[kB][gB*2+1] = pack2(vv.z, vv.w);
            __syncthreads();
            #pragma unroll
            for (int kk = 0; kk < 16; kk++) {
                u64 a[4], bb[2];
                #pragma unroll
                for (int i = 0; i < 4; i++) a[i] = As2[kk][ty*4 + i];
                bb[0] = Bs2[kk][tx*2 + 0];
                bb[1] = Bs2[kk][tx*2 + 1];
                #pragma unroll
                for (int i = 0; i < 4; i++) {
                    FMA2(acc[i][0], a[i], bb[0]);
                    FMA2(acc[i][1], a[i], bb[1]);
                }
            }
            __syncthreads();
        }

        float* op = g_op + (size_t)s * (BH_*L_*DH_) + ((size_t)bh * L_ + q0) * 64;
        #pragma unroll
        for (int i = 0; i < 4; i++) {
            float4 o;
            unpack2(acc[i][0], o.x, o.y);
            unpack2(acc[i][1], o.z, o.w);
            *(float4*)(op + (size_t)(ty*4 + i) * 64 + tx*4) = o;
        }
    }

    // zero-fill this split's strictly-non-causal columns for these 64 rows
    int zs = max(kbeg, q0 + 64) >> 2;
    int ze = min(kbeg + SPLITW, L_) >> 2;
    if (zs < ze) {
        float4 z = make_float4(0.f, 0.f, 0.f, 0.f);
        int row = tid >> 2;
        float4* rp = (float4*)(arow + (size_t)row * L_);
        for (int c4 = zs + (tid & 3); c4 < ze; c4 += 4) rp[c4] = z;
    }
}

// ---------------------------------------------------------------------------
// out = (sum_s O_partial gathered across heads) @ Wo + bo, f32x2.
// ---------------------------------------------------------------------------
__global__ __launch_bounds__(256)
void oproj_kernel(const float* __restrict__ Wo, const float* __restrict__ bo,
                  float* __restrict__ out)
{
    __shared__ u64 As2[16][66];
    __shared__ u64 Bs2[16][34];
    int tid = threadIdx.x;
    int tx = tid & 15, ty = tid >> 4;
    int m0 = blockIdx.y * 64, n0 = blockIdx.x * 64;
    int b = m0 / L_;
    int l0 = m0 - b * L_;
    u64 acc[4][2] = {};

    int ns = (l0 + 64 + SPLITW - 1) / SPLITW;
    int mA = tid >> 2, gA = tid & 3;
    int kB = tid >> 4, gB = tid & 15;

    for (int k0 = 0; k0 < 512; k0 += 16) {
        int h = k0 >> 6, dh0 = k0 & 63;
        {
            const float* base = g_op + (((size_t)(b*8 + h) * L_ + l0 + mA) * 64 + dh0 + gA*4);
            float4 a4 = *(const float4*)(base);
            for (int ss = 1; ss < ns; ss++) {
                float4 t = *(const float4*)(base + (size_t)ss * (BH_*L_*DH_));
                a4.x += t.x; a4.y += t.y; a4.z += t.z; a4.w += t.w;
            }
            As2[gA*4+0][mA] = dup2(a4.x); As2[gA*4+1][mA] = dup2(a4.y);
            As2[gA*4+2][mA] = dup2(a4.z); As2[gA*4+3][mA] = dup2(a4.w);
        }
        float4 wv = *(const float4*)(Wo + (size_t)(k0 + kB) * 512 + n0 + gB * 4);
        Bs2[kB][gB*2+0] = pack2(wv.x, wv.y);
        Bs2[kB][gB*2+1] = pack2(wv.z, wv.w);
        __syncthreads();
        #pragma unroll
        for (int kk = 0; kk < 16; kk++) {
            u64 a[4], bb[2];
            #pragma unroll
            for (int i = 0; i < 4; i++) a[i] = As2[kk][ty*4 + i];
            bb[0] = Bs2[kk][tx*2 + 0];
            bb[1] = Bs2[kk][tx*2 + 1];
            #pragma unroll
            for (int i = 0; i < 4; i++) {
                FMA2(acc[i][0], a[i], bb[0]);
                FMA2(acc[i][1], a[i], bb[1]);
            }
        }
        __syncthreads();
    }
    #pragma unroll
    for (int i = 0; i < 4; i++) {
        float4 o;
        unpack2(acc[i][0], o.x, o.y);
        unpack2(acc[i][1], o.z, o.w);
        o.x += bo[n0 + tx*4 + 0]; o.y += bo[n0 + tx*4 + 1];
        o.z += bo[n0 + tx*4 + 2]; o.w += bo[n0 + tx*4 + 3];
        *(float4*)(out + (size_t)(m0 + ty*4 + i) * 512 + n0 + tx*4) = o;
    }
}

// ---------------------------------------------------------------------------
extern "C" void kernel_launch(void* const* d_in, const int* in_sizes, int n_in,
                              void* d_out, int out_size)
{
    const float* q  = (const float*)d_in[0];
    const float* k  = (const float*)d_in[1];
    const float* v  = (const float*)d_in[2];
    const float* Wq = (const float*)d_in[4];
    const float* bq = (const float*)d_in[5];
    const float* Wk = (const float*)d_in[6];
    const float* bk = (const float*)d_in[7];
    const float* Wv = (const float*)d_in[8];
    const float* bv = (const float*)d_in[9];
    const float* E  = (const float*)d_in[10];
    const float* Wo = (const float*)d_in[11];
    const float* bo = (const float*)d_in[12];

    float* out_ptr  = (float*)d_out;
    float* attn_ptr = out_ptr + OUT_ELEMS;   // tuple order: (out, attn)

    qkv_proj_kernel<<<dim3(8, 60, 3), 256>>>(q, k, v, Wq, Wk, Wv, bq, bk, bv);
    scores_kernel<<<dim3(240, 16), 256>>>(E, attn_ptr);
    statcomb_kernel<<<(BH_ * L_ + 255) / 256, 256>>>();
    av_kernel<<<dim3(30, 16, NSPLIT), 256>>>(attn_ptr);
    oproj_kernel<<<dim3(8, 60), 256>>>(Wo, bo, out_ptr);
}

// round 6
// speedup vs baseline: 1.2404x; 1.2404x over previous
#include <cuda_runtime.h>
#include <cuda_bf16.h>
#include <cstddef>

#define B_ 2
#define L_ 1920
#define D_ 512
#define H_ 8
#define DH_ 64
#define BH_ (B_*H_)
#define NT_ 30
#define OUT_ELEMS (B_*L_*D_)
#define NSPLIT 4
#define SPLITW 480

// Scratch (device globals; no cudaMalloc allowed)
__device__ float g_qp[B_*L_*D_];
__device__ float g_kp[B_*L_*D_];
__device__ float g_vp[B_*L_*D_];
__device__ float g_op[NSPLIT * BH_*L_*DH_];
__device__ float2 g_stats[BH_*NT_*L_];
__device__ float g_M[BH_*L_];
__device__ float g_I[BH_*L_];

// ---------------------------------------------------------------------------
// QKV projection (scalar FFMA, float4 staging). Tile 64x64, micro 4x4.
// ---------------------------------------------------------------------------
__global__ __launch_bounds__(256)
void qkv_proj_kernel(const float* __restrict__ q, const float* __restrict__ k,
                     const float* __restrict__ v,
                     const float* __restrict__ Wq, const float* __restrict__ Wk,
                     const float* __restrict__ Wv,
                     const float* __restrict__ bq, const float* __restrict__ bk,
                     const float* __restrict__ bv)
{
    const float* A; const float* W; const float* bias; float* C;
    int z = blockIdx.z;
    if (z == 0)      { A = q; W = Wq; bias = bq; C = g_qp; }
    else if (z == 1) { A = k; W = Wk; bias = bk; C = g_kp; }
    else             { A = v; W = Wv; bias = bv; C = g_vp; }

    __shared__ float As[16][68];
    __shared__ float Bs[16][68];
    int tid = threadIdx.x;
    int tx = tid & 15, ty = tid >> 4;
    int m0 = blockIdx.y * 64, n0 = blockIdx.x * 64;
    float acc[4][4] = {};

    int mA = tid >> 2, gA = tid & 3;
    int kB = tid >> 4, gB = tid & 15;

    for (int k0 = 0; k0 < 512; k0 += 16) {
        float4 av = *(const float4*)(A + (size_t)(m0 + mA) * 512 + k0 + gA * 4);
        As[gA*4+0][mA] = av.x; As[gA*4+1][mA] = av.y;
        As[gA*4+2][mA] = av.z; As[gA*4+3][mA] = av.w;
        float4 wv = *(const float4*)(W + (size_t)(k0 + kB) * 512 + n0 + gB * 4);
        Bs[kB][gB*4+0] = wv.x; Bs[kB][gB*4+1] = wv.y;
        Bs[kB][gB*4+2] = wv.z; Bs[kB][gB*4+3] = wv.w;
        __syncthreads();
        #pragma unroll
        for (int kk = 0; kk < 16; kk++) {
            float a[4], b[4];
            #pragma unroll
            for (int i = 0; i < 4; i++) a[i] = As[kk][ty * 4 + i];
            #pragma unroll
            for (int j = 0; j < 4; j++) b[j] = Bs[kk][tx * 4 + j];
            #pragma unroll
            for (int i = 0; i < 4; i++)
                #pragma unroll
                for (int j = 0; j < 4; j++)
                    acc[i][j] += a[i] * b[j];
        }
        __syncthreads();
    }
    #pragma unroll
    for (int i = 0; i < 4; i++) {
        float4 o;
        o.x = acc[i][0] + bias[n0 + tx*4 + 0];
        o.y = acc[i][1] + bias[n0 + tx*4 + 1];
        o.z = acc[i][2] + bias[n0 + tx*4 + 2];
        o.w = acc[i][3] + bias[n0 + tx*4 + 3];
        *(float4*)(C + (size_t)(m0 + ty*4 + i) * 512 + n0 + tx*4) = o;
    }
}

// ---------------------------------------------------------------------------
// Scores (scalar FFMA). Tile 128q x 64k, 256 thr, micro 8x4.
// logits = (Q.K + Q.E[rel]) * 0.125 ; per-(row, 64-k-tile) stats.
// Triangular grid over (qt128, kt64): kt in [0, 2qt+2), 240 blocks.
// E-indexing identical to the verified R5 kernel.
// ---------------------------------------------------------------------------
__global__ __launch_bounds__(256)
void scores_kernel(const float* __restrict__ E, float* __restrict__ attn)
{
    int idx = blockIdx.x;
    int qt = (int)((sqrtf(4.f * idx + 1.f) - 1.f) * 0.5f);
    while ((qt + 1) * (qt + 2) <= idx) qt++;
    while (qt * (qt + 1) > idx) qt--;
    int kt = idx - qt * (qt + 1);         // in [0, 2qt+2)

    int bh = blockIdx.y;
    int b = bh >> 3, h = bh & 7;
    int q0 = qt * 128, k0 = kt * 64;

    __shared__ float Qsf[16][132];
    __shared__ float Ksf[16][68];
    __shared__ float Esf[16][196];

    int tid = threadIdx.x;
    int tx = tid & 15, ty = tid >> 4;
    float acc[8][4] = {};

    const float* qbase = g_qp + (size_t)b * L_ * 512 + h * 64;
    const float* kbase = g_kp + (size_t)b * L_ * 512 + h * 64;
    // Esf[ro] holds E row (rbase + ro + 1); ro = kc - qr + 127 in [0,191]
    int rbase = k0 - q0 + 1792;

    int mQ = tid >> 1, gQ = tid & 1;      // Q: row mQ, 8-dim half gQ
    int kB = tid >> 2, gB = tid & 3;      // K: row kB, float4 gB

    for (int dc = 0; dc < 4; dc++) {
        int d0 = dc * 16;
        {
            float4 qa = *(const float4*)(qbase + (size_t)(q0 + mQ) * 512 + d0 + gQ*8);
            float4 qb = *(const float4*)(qbase + (size_t)(q0 + mQ) * 512 + d0 + gQ*8 + 4);
            Qsf[gQ*8+0][mQ] = qa.x; Qsf[gQ*8+1][mQ] = qa.y;
            Qsf[gQ*8+2][mQ] = qa.z; Qsf[gQ*8+3][mQ] = qa.w;
            Qsf[gQ*8+4][mQ] = qb.x; Qsf[gQ*8+5][mQ] = qb.y;
            Qsf[gQ*8+6][mQ] = qb.z; Qsf[gQ*8+7][mQ] = qb.w;
            float4 kv = *(const float4*)(kbase + (size_t)(k0 + kB) * 512 + d0 + gB*4);
            Ksf[gB*4+0][kB] = kv.x; Ksf[gB*4+1][kB] = kv.y;
            Ksf[gB*4+2][kB] = kv.z; Ksf[gB*4+3][kB] = kv.w;
        }
        #pragma unroll
        for (int r = 0; r < 3; r++) {
            int i2 = tid + r * 256;           // 0..767
            int ro = i2 >> 2, g = i2 & 3;     // ro 0..191
            int rr = rbase + ro;
            float4 ev = make_float4(0.f, 0.f, 0.f, 0.f);
            if (rr >= 0 && rr < L_)
                ev = *(const float4*)(E + (size_t)(rr + 1) * 512 + h * 64 + d0 + g*4);
            Esf[g*4+0][ro] = ev.x; Esf[g*4+1][ro] = ev.y;
            Esf[g*4+2][ro] = ev.z; Esf[g*4+3][ro] = ev.w;
        }
        __syncthreads();
        int tbase = 4*tx - 8*ty + 127;        // (col - row + 127) at (i=0,j=0)
        #pragma unroll
        for (int dd = 0; dd < 16; dd++) {
            float a[8], kv[4], e[11];
            #pragma unroll
            for (int i = 0; i < 8; i++) a[i] = Qsf[dd][ty*8 + i];
            #pragma unroll
            for (int j = 0; j < 4; j++) kv[j] = Ksf[dd][tx*4 + j];
            #pragma unroll
            for (int t = 0; t < 11; t++) e[t] = Esf[dd][tbase - 7 + t];
            #pragma unroll
            for (int i = 0; i < 8; i++)
                #pragma unroll
                for (int j = 0; j < 4; j++)
                    acc[i][j] += a[i] * (kv[j] + e[7 - i + j]);
        }
        __syncthreads();
    }

    bool partial = (k0 + 63 > q0);
    #pragma unroll
    for (int i = 0; i < 8; i++) {
        int row = ty * 8 + i;
        float v[4];
        #pragma unroll
        for (int j = 0; j < 4; j++) v[j] = acc[i][j] * 0.125f;
        *(float4*)(attn + ((size_t)bh * L_ + q0 + row) * L_ + k0 + tx*4) =
            make_float4(v[0], v[1], v[2], v[3]);

        int qrow = q0 + row;
        float m = -1e30f;
        #pragma unroll
        for (int j = 0; j < 4; j++) {
            bool valid = !partial || (k0 + tx*4 + j <= qrow);
            if (valid) m = fmaxf(m, v[j]);
        }
        #pragma unroll
        for (int off = 8; off > 0; off >>= 1)
            m = fmaxf(m, __shfl_xor_sync(0xffffffffu, m, off, 16));
        float s = 0.f;
        #pragma unroll
        for (int j = 0; j < 4; j++) {
            bool valid = !partial || (k0 + tx*4 + j <= qrow);
            if (valid) s += __expf(v[j] - m);
        }
        #pragma unroll
        for (int off = 8; off > 0; off >>= 1)
            s += __shfl_xor_sync(0xffffffffu, s, off, 16);
        if (tx == 0)
            g_stats[((size_t)bh * NT_ + kt) * L_ + qrow] = make_float2(m, s);
    }
}

// ---------------------------------------------------------------------------
// Combine per-tile stats into per-row (max, 1/sum).
// ---------------------------------------------------------------------------
__global__ __launch_bounds__(256)
void statcomb_kernel()
{
    int p = blockIdx.x * 256 + threadIdx.x;
    if (p >= BH_ * L_) return;
    int bh = p / L_, q = p - bh * L_;
    int nt = q / 64 + 1;

    const float2* st = g_stats + (size_t)bh * NT_ * L_ + q;
    float M = -1e30f;
    for (int t = 0; t < nt; t++) M = fmaxf(M, st[(size_t)t * L_].x);
    float S = 0.f;
    for (int t = 0; t < nt; t++) {
        float2 v = st[(size_t)t * L_];
        S += v.y * __expf(v.x - M);
    }
    g_M[p] = M;
    g_I[p] = 1.f / S;
}

// ---------------------------------------------------------------------------
// Fused normalize + AV (split-K, scalar FFMA) + zerofill of k>q columns.
// ---------------------------------------------------------------------------
__global__ __launch_bounds__(256)
void av_kernel(float* __restrict__ attn)
{
    int qt = blockIdx.x;
    int bh = blockIdx.y;
    int s  = blockIdx.z;
    int b = bh >> 3, h = bh & 7;
    int q0 = qt * 64;
    int tid = threadIdx.x;

    int kbeg = s * SPLITW;
    int kend = min(q0 + 64, kbeg + SPLITW);

    float* arow = attn + ((size_t)bh * L_ + q0) * L_;

    if (kbeg < kend) {
        __shared__ float As[16][68];
        __shared__ float Bs[16][68];
        __shared__ float sM[64];
        __shared__ float sI[64];
        int tx = tid & 15, ty = tid >> 4;
        float acc[4][4] = {};

        if (tid < 64) {
            sM[tid] = g_M[(size_t)bh * L_ + q0 + tid];
            sI[tid] = g_I[(size_t)bh * L_ + q0 + tid];
        }
        __syncthreads();

        const float* vbase = g_vp + (size_t)b * L_ * 512 + h * 64;
        int mA = tid >> 2, gA = tid & 3;
        int kB = tid >> 4, gB = tid & 15;
        float Mr = sM[mA], Ir = sI[mA];
        int qrow = q0 + mA;

        for (int k0 = kbeg; k0 < kend; k0 += 16) {
            float4 xv = *(float4*)(arow + (size_t)mA * L_ + k0 + gA * 4);
            int kb = k0 + gA * 4;
            float4 p;
            p.x = (kb + 0 <= qrow) ? __expf(xv.x - Mr) * Ir : 0.f;
            p.y = (kb + 1 <= qrow) ? __expf(xv.y - Mr) * Ir : 0.f;
            p.z = (kb + 2 <= qrow) ? __expf(xv.z - Mr) * Ir : 0.f;
            p.w = (kb + 3 <= qrow) ? __expf(xv.w - Mr) * Ir : 0.f;
            *(float4*)(arow + (size_t)mA * L_ + k0 + gA * 4) = p;
            As[gA*4+0][mA] = p.x; As[gA*4+1][mA] = p.y;
            As[gA*4+2][mA] = p.z; As[gA*4+3][mA] = p.w;
            float4 vv = *(const float4*)(vbase + (size_t)(k0 + kB) * 512 + gB * 4);
            Bs[kB][gB*4+0] = vv.x; Bs[kB][gB*4+1] = vv.y;
            Bs[kB][gB*4+2] = vv.z; Bs[kB][gB*4+3] = vv.w;
            __syncthreads();
            #pragma unroll
            for (int kk = 0; kk < 16; kk++) {
                float a[4], bv[4];
                #pragma unroll
                for (int i = 0; i < 4; i++) a[i] = As[kk][ty * 4 + i];
                #pragma unroll
                for (int j = 0; j < 4; j++) bv[j] = Bs[kk][tx * 4 + j];
                #pragma unroll
                for (int i = 0; i < 4; i++)
                    #pragma unroll
                    for (int j = 0; j < 4; j++)
                        acc[i][j] += a[i] * bv[j];
            }
            __syncthreads();
        }

        float* op = g_op + (size_t)s * (BH_*L_*DH_) + ((size_t)bh * L_ + q0) * 64;
        #pragma unroll
        for (int i = 0; i < 4; i++) {
            float4 o = make_float4(acc[i][0], acc[i][1], acc[i][2], acc[i][3]);
            *(float4*)(op + (size_t)(ty*4 + i) * 64 + tx*4) = o;
        }
    }

    // zero-fill this split's strictly-non-causal columns for these 64 rows
    int zs = max(kbeg, q0 + 64) >> 2;
    int ze = min(kbeg + SPLITW, L_) >> 2;
    if (zs < ze) {
        float4 z = make_float4(0.f, 0.f, 0.f, 0.f);
        int row = tid >> 2;
        float4* rp = (float4*)(arow + (size_t)row * L_);
        for (int c4 = zs + (tid & 3); c4 < ze; c4 += 4) rp[c4] = z;
    }
}

// ---------------------------------------------------------------------------
// out = (sum_s O_partial gathered across heads) @ Wo + bo (scalar FFMA).
// ---------------------------------------------------------------------------
__global__ __launch_bounds__(256)
void oproj_kernel(const float* __restrict__ Wo, const float* __restrict__ bo,
                  float* __restrict__ out)
{
    __shared__ float As[16][68];
    __shared__ float Bs[16][68];
    int tid = threadIdx.x;
    int tx = tid & 15, ty = tid >> 4;
    int m0 = blockIdx.y * 64, n0 = blockIdx.x * 64;
    int b = m0 / L_;
    int l0 = m0 - b * L_;
    float acc[4][4] = {};

    int ns = (l0 + 64 + SPLITW - 1) / SPLITW;
    int mA = tid >> 2, gA = tid & 3;
    int kB = tid >> 4, gB = tid & 15;

    for (int k0 = 0; k0 < 512; k0 += 16) {
        int h = k0 >> 6, dh0 = k0 & 63;
        {
            const float* base = g_op + (((size_t)(b*8 + h) * L_ + l0 + mA) * 64 + dh0 + gA*4);
            float4 a4 = *(const float4*)(base);
            for (int ss = 1; ss < ns; ss++) {
                float4 t = *(const float4*)(base + (size_t)ss * (BH_*L_*DH_));
                a4.x += t.x; a4.y += t.y; a4.z += t.z; a4.w += t.w;
            }
            As[gA*4+0][mA] = a4.x; As[gA*4+1][mA] = a4.y;
            As[gA*4+2][mA] = a4.z; As[gA*4+3][mA] = a4.w;
        }
        float4 wv = *(const float4*)(Wo + (size_t)(k0 + kB) * 512 + n0 + gB * 4);
        Bs[kB][gB*4+0] = wv.x; Bs[kB][gB*4+1] = wv.y;
        Bs[kB][gB*4+2] = wv.z; Bs[kB][gB*4+3] = wv.w;
        __syncthreads();
        #pragma unroll
        for (int kk = 0; kk < 16; kk++) {
            float a[4], bv[4];
            #pragma unroll
            for (int i = 0; i < 4; i++) a[i] = As[kk][ty * 4 + i];
            #pragma unroll
            for (int j = 0; j < 4; j++) bv[j] = Bs[kk][tx * 4 + j];
            #pragma unroll
            for (int i = 0; i < 4; i++)
                #pragma unroll
                for (int j = 0; j < 4; j++)
                    acc[i][j] += a[i] * bv[j];
        }
        __syncthreads();
    }
    #pragma unroll
    for (int i = 0; i < 4; i++) {
        float4 o;
        o.x = acc[i][0] + bo[n0 + tx*4 + 0];
        o.y = acc[i][1] + bo[n0 + tx*4 + 1];
        o.z = acc[i][2] + bo[n0 + tx*4 + 2];
        o.w = acc[i][3] + bo[n0 + tx*4 + 3];
        *(float4*)(out + (size_t)(m0 + ty*4 + i) * 512 + n0 + tx*4) = o;
    }
}

// ---------------------------------------------------------------------------
extern "C" void kernel_launch(void* const* d_in, const int* in_sizes, int n_in,
                              void* d_out, int out_size)
{
    const float* q  = (const float*)d_in[0];
    const float* k  = (const float*)d_in[1];
    const float* v  = (const float*)d_in[2];
    const float* Wq = (const float*)d_in[4];
    const float* bq = (const float*)d_in[5];
    const float* Wk = (const float*)d_in[6];
    const float* bk = (const float*)d_in[7];
    const float* Wv = (const float*)d_in[8];
    const float* bv = (const float*)d_in[9];
    const float* E  = (const float*)d_in[10];
    const float* Wo = (const float*)d_in[11];
    const float* bo = (const float*)d_in[12];

    float* out_ptr  = (float*)d_out;
    float* attn_ptr = out_ptr + OUT_ELEMS;   // tuple order: (out, attn)

    qkv_proj_kernel<<<dim3(8, 60, 3), 256>>>(q, k, v, Wq, Wk, Wv, bq, bk, bv);
    scores_kernel<<<dim3(240, 16), 256>>>(E, attn_ptr);
    statcomb_kernel<<<(BH_ * L_ + 255) / 256, 256>>>();
    av_kernel<<<dim3(30, 16, NSPLIT), 256>>>(attn_ptr);
    oproj_kernel<<<dim3(8, 60), 256>>>(Wo, bo, out_ptr);
}

// round 7
// speedup vs baseline: 1.2770x; 1.0295x over previous
#include <cuda_runtime.h>
#include <cuda_bf16.h>
#include <cstddef>

#define B_ 2
#define L_ 1920
#define D_ 512
#define H_ 8
#define DH_ 64
#define BH_ (B_*H_)
#define NT_ 30
#define OUT_ELEMS (B_*L_*D_)
#define NSPLIT 4
#define SPLITW 480

// Scratch (device globals; no cudaMalloc allowed)
__device__ float g_qp[B_*L_*D_];
__device__ float g_kp[B_*L_*D_];
__device__ float g_vp[B_*L_*D_];
__device__ float g_op[NSPLIT * BH_*L_*DH_];
__device__ float2 g_stats[BH_*NT_*L_];
__device__ float g_M[BH_*L_];
__device__ float g_I[BH_*L_];

// ---------------------------------------------------------------------------
// QKV projection (scalar FFMA, float4 staging). Tile 64x64, micro 4x4.
// ---------------------------------------------------------------------------
__global__ __launch_bounds__(256)
void qkv_proj_kernel(const float* __restrict__ q, const float* __restrict__ k,
                     const float* __restrict__ v,
                     const float* __restrict__ Wq, const float* __restrict__ Wk,
                     const float* __restrict__ Wv,
                     const float* __restrict__ bq, const float* __restrict__ bk,
                     const float* __restrict__ bv)
{
    const float* A; const float* W; const float* bias; float* C;
    int z = blockIdx.z;
    if (z == 0)      { A = q; W = Wq; bias = bq; C = g_qp; }
    else if (z == 1) { A = k; W = Wk; bias = bk; C = g_kp; }
    else             { A = v; W = Wv; bias = bv; C = g_vp; }

    __shared__ float As[16][68];
    __shared__ float Bs[16][68];
    int tid = threadIdx.x;
    int tx = tid & 15, ty = tid >> 4;
    int m0 = blockIdx.y * 64, n0 = blockIdx.x * 64;
    float acc[4][4] = {};

    int mA = tid >> 2, gA = tid & 3;
    int kB = tid >> 4, gB = tid & 15;

    for (int k0 = 0; k0 < 512; k0 += 16) {
        float4 av = *(const float4*)(A + (size_t)(m0 + mA) * 512 + k0 + gA * 4);
        As[gA*4+0][mA] = av.x; As[gA*4+1][mA] = av.y;
        As[gA*4+2][mA] = av.z; As[gA*4+3][mA] = av.w;
        float4 wv = *(const float4*)(W + (size_t)(k0 + kB) * 512 + n0 + gB * 4);
        Bs[kB][gB*4+0] = wv.x; Bs[kB][gB*4+1] = wv.y;
        Bs[kB][gB*4+2] = wv.z; Bs[kB][gB*4+3] = wv.w;
        __syncthreads();
        #pragma unroll
        for (int kk = 0; kk < 16; kk++) {
            float a[4], b[4];
            #pragma unroll
            for (int i = 0; i < 4; i++) a[i] = As[kk][ty * 4 + i];
            #pragma unroll
            for (int j = 0; j < 4; j++) b[j] = Bs[kk][tx * 4 + j];
            #pragma unroll
            for (int i = 0; i < 4; i++)
                #pragma unroll
                for (int j = 0; j < 4; j++)
                    acc[i][j] += a[i] * b[j];
        }
        __syncthreads();
    }
    #pragma unroll
    for (int i = 0; i < 4; i++) {
        float4 o;
        o.x = acc[i][0] + bias[n0 + tx*4 + 0];
        o.y = acc[i][1] + bias[n0 + tx*4 + 1];
        o.z = acc[i][2] + bias[n0 + tx*4 + 2];
        o.w = acc[i][3] + bias[n0 + tx*4 + 3];
        *(float4*)(C + (size_t)(m0 + ty*4 + i) * 512 + n0 + tx*4) = o;
    }
}

// ---------------------------------------------------------------------------
// Scores, 64x64 tile (R3-verified indexing), FULL tile staged once in
// dynamic smem: Qs[64][68] + Ks[64][68] + Es[64][132]  (68.6 KB).
// One __syncthreads per block; 64-deep straight-line mainloop.
// logits = (Q.K + Q.E[rel]) * 0.125 ; per-(row,ktile) softmax stats.
// ---------------------------------------------------------------------------
#define QS_OFF 0
#define KS_OFF (64*68)
#define ES_OFF (2*64*68)
#define SC_SMEM ((2*64*68 + 64*132) * 4)   // 68608 bytes

__global__ __launch_bounds__(256)
void scores_kernel(const float* __restrict__ E, float* __restrict__ attn)
{
    extern __shared__ float sm[];
    float* Qs = sm + QS_OFF;    // [dd][m]  stride 68
    float* Ks = sm + KS_OFF;    // [dd][m]  stride 68
    float* Es = sm + ES_OFF;    // [dd][ro] stride 132

    int idx = blockIdx.x;
    int qt = (int)((sqrtf(8.f * idx + 1.f) - 1.f) * 0.5f);
    while ((qt + 1) * (qt + 2) / 2 <= idx) qt++;
    while (qt * (qt + 1) / 2 > idx) qt--;
    int kt = idx - qt * (qt + 1) / 2;

    int bh = blockIdx.y;
    int b = bh >> 3, h = bh & 7;
    int q0 = qt * 64, k0 = kt * 64;

    int tid = threadIdx.x;
    int tx = tid & 15, ty = tid >> 4;

    const float* qbase = g_qp + (size_t)b * L_ * 512 + h * 64;
    const float* kbase = g_kp + (size_t)b * L_ * 512 + h * 64;
    // Es[ro] holds E row (rbase + ro + 1); ro = (col - row) + 63 in [0,126]
    int rbase = k0 - q0 + 1856;          // verified in R2/R3

    // ---- stage Q and K: 64 rows x 16 float4 each ----
    #pragma unroll
    for (int r = 0; r < 4; r++) {
        int u = tid + r * 256;
        int m = u >> 4, g = u & 15;
        float4 qv = *(const float4*)(qbase + (size_t)(q0 + m) * 512 + g * 4);
        Qs[(g*4+0)*68 + m] = qv.x; Qs[(g*4+1)*68 + m] = qv.y;
        Qs[(g*4+2)*68 + m] = qv.z; Qs[(g*4+3)*68 + m] = qv.w;
        float4 kv = *(const float4*)(kbase + (size_t)(k0 + m) * 512 + g * 4);
        Ks[(g*4+0)*68 + m] = kv.x; Ks[(g*4+1)*68 + m] = kv.y;
        Ks[(g*4+2)*68 + m] = kv.z; Ks[(g*4+3)*68 + m] = kv.w;
    }
    // ---- stage E band: 127 rows x 16 float4 ----
    #pragma unroll
    for (int r = 0; r < 8; r++) {
        int u = tid + r * 256;
        if (u < 127 * 16) {
            int ro = u >> 4, g = u & 15;
            int rr = rbase + ro;
            float4 ev = make_float4(0.f, 0.f, 0.f, 0.f);
            if (rr >= 0 && rr < L_)
                ev = *(const float4*)(E + (size_t)(rr + 1) * 512 + h * 64 + g * 4);
            Es[(g*4+0)*132 + ro] = ev.x; Es[(g*4+1)*132 + ro] = ev.y;
            Es[(g*4+2)*132 + ro] = ev.z; Es[(g*4+3)*132 + ro] = ev.w;
        }
    }
    __syncthreads();

    float acc[4][4] = {};
    int ebase = 4 * (tx - ty) + 60;      // + (j - i + 3) => ro
    #pragma unroll 16
    for (int dd = 0; dd < 64; dd++) {
        float a[4], kv[4], ev[7];
        #pragma unroll
        for (int i = 0; i < 4; i++) a[i] = Qs[dd*68 + ty*4 + i];
        #pragma unroll
        for (int j = 0; j < 4; j++) kv[j] = Ks[dd*68 + tx*4 + j];
        #pragma unroll
        for (int t = 0; t < 7; t++) ev[t] = Es[dd*132 + ebase + t];
        #pragma unroll
        for (int i = 0; i < 4; i++)
            #pragma unroll
            for (int j = 0; j < 4; j++)
                acc[i][j] += a[i] * (kv[j] + ev[j - i + 3]);
    }

    bool diag = (qt == kt);
    float* out = attn + ((size_t)bh * L_ + q0) * L_ + k0;
    #pragma unroll
    for (int i = 0; i < 4; i++) {
        float v[4];
        #pragma unroll
        for (int j = 0; j < 4; j++) v[j] = acc[i][j] * 0.125f;
        *(float4*)(out + (size_t)(ty*4 + i) * L_ + tx*4) =
            make_float4(v[0], v[1], v[2], v[3]);

        int row = ty * 4 + i;
        float m = -1e30f;
        #pragma unroll
        for (int j = 0; j < 4; j++) {
            bool valid = !diag || (tx * 4 + j <= row);
            if (valid) m = fmaxf(m, v[j]);
        }
        #pragma unroll
        for (int off = 8; off > 0; off >>= 1)
            m = fmaxf(m, __shfl_xor_sync(0xffffffffu, m, off, 16));
        float s = 0.f;
        #pragma unroll
        for (int j = 0; j < 4; j++) {
            bool valid = !diag || (tx * 4 + j <= row);
            if (valid) s += __expf(v[j] - m);
        }
        #pragma unroll
        for (int off = 8; off > 0; off >>= 1)
            s += __shfl_xor_sync(0xffffffffu, s, off, 16);
        if (tx == 0)
            g_stats[((size_t)bh * NT_ + kt) * L_ + q0 + row] = make_float2(m, s);
    }
}

// ---------------------------------------------------------------------------
// Combine per-tile stats into per-row (max, 1/sum).
// ---------------------------------------------------------------------------
__global__ __launch_bounds__(256)
void statcomb_kernel()
{
    int p = blockIdx.x * 256 + threadIdx.x;
    if (p >= BH_ * L_) return;
    int bh = p / L_, q = p - bh * L_;
    int nt = q / 64 + 1;

    const float2* st = g_stats + (size_t)bh * NT_ * L_ + q;
    float M = -1e30f;
    for (int t = 0; t < nt; t++) M = fmaxf(M, st[(size_t)t * L_].x);
    float S = 0.f;
    for (int t = 0; t < nt; t++) {
        float2 v = st[(size_t)t * L_];
        S += v.y * __expf(v.x - M);
    }
    g_M[p] = M;
    g_I[p] = 1.f / S;
}

// ---------------------------------------------------------------------------
// Fused normalize + AV (split-K, scalar FFMA) + zerofill of k>q columns.
// ---------------------------------------------------------------------------
__global__ __launch_bounds__(256)
void av_kernel(float* __restrict__ attn)
{
    int qt = blockIdx.x;
    int bh = blockIdx.y;
    int s  = blockIdx.z;
    int b = bh >> 3, h = bh & 7;
    int q0 = qt * 64;
    int tid = threadIdx.x;

    int kbeg = s * SPLITW;
    int kend = min(q0 + 64, kbeg + SPLITW);

    float* arow = attn + ((size_t)bh * L_ + q0) * L_;

    if (kbeg < kend) {
        __shared__ float As[16][68];
        __shared__ float Bs[16][68];
        __shared__ float sM[64];
        __shared__ float sI[64];
        int tx = tid & 15, ty = tid >> 4;
        float acc[4][4] = {};

        if (tid < 64) {
            sM[tid] = g_M[(size_t)bh * L_ + q0 + tid];
            sI[tid] = g_I[(size_t)bh * L_ + q0 + tid];
        }
        __syncthreads();

        const float* vbase = g_vp + (size_t)b * L_ * 512 + h * 64;
        int mA = tid >> 2, gA = tid & 3;
        int kB = tid >> 4, gB = tid & 15;
        float Mr = sM[mA], Ir = sI[mA];
        int qrow = q0 + mA;

        for (int k0 = kbeg; k0 < kend; k0 += 16) {
            float4 xv = *(float4*)(arow + (size_t)mA * L_ + k0 + gA * 4);
            int kb = k0 + gA * 4;
            float4 p;
            p.x = (kb + 0 <= qrow) ? __expf(xv.x - Mr) * Ir : 0.f;
            p.y = (kb + 1 <= qrow) ? __expf(xv.y - Mr) * Ir : 0.f;
            p.z = (kb + 2 <= qrow) ? __expf(xv.z - Mr) * Ir : 0.f;
            p.w = (kb + 3 <= qrow) ? __expf(xv.w - Mr) * Ir : 0.f;
            *(float4*)(arow + (size_t)mA * L_ + k0 + gA * 4) = p;
            As[gA*4+0][mA] = p.x; As[gA*4+1][mA] = p.y;
            As[gA*4+2][mA] = p.z; As[gA*4+3][mA] = p.w;
            float4 vv = *(const float4*)(vbase + (size_t)(k0 + kB) * 512 + gB * 4);
            Bs[kB][gB*4+0] = vv.x; Bs[kB][gB*4+1] = vv.y;
            Bs[kB][gB*4+2] = vv.z; Bs[kB][gB*4+3] = vv.w;
            __syncthreads();
            #pragma unroll
            for (int kk = 0; kk < 16; kk++) {
                float a[4], bv[4];
                #pragma unroll
                for (int i = 0; i < 4; i++) a[i] = As[kk][ty * 4 + i];
                #pragma unroll
                for (int j = 0; j < 4; j++) bv[j] = Bs[kk][tx * 4 + j];
                #pragma unroll
                for (int i = 0; i < 4; i++)
                    #pragma unroll
                    for (int j = 0; j < 4; j++)
                        acc[i][j] += a[i] * bv[j];
            }
            __syncthreads();
        }

        float* op = g_op + (size_t)s * (BH_*L_*DH_) + ((size_t)bh * L_ + q0) * 64;
        #pragma unroll
        for (int i = 0; i < 4; i++) {
            float4 o = make_float4(acc[i][0], acc[i][1], acc[i][2], acc[i][3]);
            *(float4*)(op + (size_t)(ty*4 + i) * 64 + tx*4) = o;
        }
    }

    // zero-fill this split's strictly-non-causal columns for these 64 rows
    int zs = max(kbeg, q0 + 64) >> 2;
    int ze = min(kbeg + SPLITW, L_) >> 2;
    if (zs < ze) {
        float4 z = make_float4(0.f, 0.f, 0.f, 0.f);
        int row = tid >> 2;
        float4* rp = (float4*)(arow + (size_t)row * L_);
        for (int c4 = zs + (tid & 3); c4 < ze; c4 += 4) rp[c4] = z;
    }
}

// ---------------------------------------------------------------------------
// out = (sum_s O_partial gathered across heads) @ Wo + bo (scalar FFMA).
// ---------------------------------------------------------------------------
__global__ __launch_bounds__(256)
void oproj_kernel(const float* __restrict__ Wo, const float* __restrict__ bo,
                  float* __restrict__ out)
{
    __shared__ float As[16][68];
    __shared__ float Bs[16][68];
    int tid = threadIdx.x;
    int tx = tid & 15, ty = tid >> 4;
    int m0 = blockIdx.y * 64, n0 = blockIdx.x * 64;
    int b = m0 / L_;
    int l0 = m0 - b * L_;
    float acc[4][4] = {};

    int ns = (l0 + 64 + SPLITW - 1) / SPLITW;
    int mA = tid >> 2, gA = tid & 3;
    int kB = tid >> 4, gB = tid & 15;

    for (int k0 = 0; k0 < 512; k0 += 16) {
        int h = k0 >> 6, dh0 = k0 & 63;
        {
            const float* base = g_op + (((size_t)(b*8 + h) * L_ + l0 + mA) * 64 + dh0 + gA*4);
            float4 a4 = *(const float4*)(base);
            for (int ss = 1; ss < ns; ss++) {
                float4 t = *(const float4*)(base + (size_t)ss * (BH_*L_*DH_));
                a4.x += t.x; a4.y += t.y; a4.z += t.z; a4.w += t.w;
            }
            As[gA*4+0][mA] = a4.x; As[gA*4+1][mA] = a4.y;
            As[gA*4+2][mA] = a4.z; As[gA*4+3][mA] = a4.w;
        }
        float4 wv = *(const float4*)(Wo + (size_t)(k0 + kB) * 512 + n0 + gB * 4);
        Bs[kB][gB*4+0] = wv.x; Bs[kB][gB*4+1] = wv.y;
        Bs[kB][gB*4+2] = wv.z; Bs[kB][gB*4+3] = wv.w;
        __syncthreads();
        #pragma unroll
        for (int kk = 0; kk < 16; kk++) {
            float a[4], bv[4];
            #pragma unroll
            for (int i = 0; i < 4; i++) a[i] = As[kk][ty * 4 + i];
            #pragma unroll
            for (int j = 0; j < 4; j++) bv[j] = Bs[kk][tx * 4 + j];
            #pragma unroll
            for (int i = 0; i < 4; i++)
                #pragma unroll
                for (int j = 0; j < 4; j++)
                    acc[i][j] += a[i] * bv[j];
        }
        __syncthreads();
    }
    #pragma unroll
    for (int i = 0; i < 4; i++) {
        float4 o;
        o.x = acc[i][0] + bo[n0 + tx*4 + 0];
        o.y = acc[i][1] + bo[n0 + tx*4 + 1];
        o.z = acc[i][2] + bo[n0 + tx*4 + 2];
        o.w = acc[i][3] + bo[n0 + tx*4 + 3];
        *(float4*)(out + (size_t)(m0 + ty*4 + i) * 512 + n0 + tx*4) = o;
    }
}

// ---------------------------------------------------------------------------
extern "C" void kernel_launch(void* const* d_in, const int* in_sizes, int n_in,
                              void* d_out, int out_size)
{
    const float* q  = (const float*)d_in[0];
    const float* k  = (const float*)d_in[1];
    const float* v  = (const float*)d_in[2];
    const float* Wq = (const float*)d_in[4];
    const float* bq = (const float*)d_in[5];
    const float* Wk = (const float*)d_in[6];
    const float* bk = (const float*)d_in[7];
    const float* Wv = (const float*)d_in[8];
    const float* bv = (const float*)d_in[9];
    const float* E  = (const float*)d_in[10];
    const float* Wo = (const float*)d_in[11];
    const float* bo = (const float*)d_in[12];

    float* out_ptr  = (float*)d_out;
    float* attn_ptr = out_ptr + OUT_ELEMS;   // tuple order: (out, attn)

    cudaFuncSetAttribute(scores_kernel,
                         cudaFuncAttributeMaxDynamicSharedMemorySize, SC_SMEM);

    qkv_proj_kernel<<<dim3(8, 60, 3), 256>>>(q, k, v, Wq, Wk, Wv, bq, bk, bv);
    scores_kernel<<<dim3(465, 16), 256, SC_SMEM>>>(E, attn_ptr);
    statcomb_kernel<<<(BH_ * L_ + 255) / 256, 256>>>();
    av_kernel<<<dim3(30, 16, NSPLIT), 256>>>(attn_ptr);
    oproj_kernel<<<dim3(8, 60), 256>>>(Wo, bo, out_ptr);
}

// round 8
// speedup vs baseline: 1.2965x; 1.0152x over previous
#include <cuda_runtime.h>
#include <cuda_bf16.h>
#include <cstddef>

#define B_ 2
#define L_ 1920
#define D_ 512
#define H_ 8
#define DH_ 64
#define BH_ (B_*H_)
#define NT_ 30
#define OUT_ELEMS (B_*L_*D_)
#define NSPLIT 4
#define SPLITW 480

// Scratch (device globals; no cudaMalloc allowed)
__device__ float g_qp[B_*L_*D_];
__device__ float g_kp[B_*L_*D_];
__device__ float g_vp[B_*L_*D_];
__device__ float g_op[NSPLIT * BH_*L_*DH_];
__device__ float2 g_stats[BH_*NT_*L_];
__device__ float g_M[BH_*L_];
__device__ float g_I[BH_*L_];

// ---------------------------------------------------------------------------
// QKV projection. Tile 128x64, 256 thr, micro 8x4.
// ---------------------------------------------------------------------------
__global__ __launch_bounds__(256)
void qkv_proj_kernel(const float* __restrict__ q, const float* __restrict__ k,
                     const float* __restrict__ v,
                     const float* __restrict__ Wq, const float* __restrict__ Wk,
                     const float* __restrict__ Wv,
                     const float* __restrict__ bq, const float* __restrict__ bk,
                     const float* __restrict__ bv)
{
    const float* A; const float* W; const float* bias; float* C;
    int z = blockIdx.z;
    if (z == 0)      { A = q; W = Wq; bias = bq; C = g_qp; }
    else if (z == 1) { A = k; W = Wk; bias = bk; C = g_kp; }
    else             { A = v; W = Wv; bias = bv; C = g_vp; }

    __shared__ float As[16][132];
    __shared__ float Bs[16][68];
    int tid = threadIdx.x;
    int tx = tid & 15, ty = tid >> 4;
    int m0 = blockIdx.y * 128, n0 = blockIdx.x * 64;
    float acc[8][4] = {};

    int mA = tid >> 2, gA = tid & 3;      // A rows mA and 64+mA
    int kB = tid >> 4, gB = tid & 15;

    for (int k0 = 0; k0 < 512; k0 += 16) {
        float4 a0 = *(const float4*)(A + (size_t)(m0 + mA) * 512 + k0 + gA * 4);
        As[gA*4+0][mA] = a0.x; As[gA*4+1][mA] = a0.y;
        As[gA*4+2][mA] = a0.z; As[gA*4+3][mA] = a0.w;
        float4 a1 = *(const float4*)(A + (size_t)(m0 + 64 + mA) * 512 + k0 + gA * 4);
        As[gA*4+0][64+mA] = a1.x; As[gA*4+1][64+mA] = a1.y;
        As[gA*4+2][64+mA] = a1.z; As[gA*4+3][64+mA] = a1.w;
        float4 wv = *(const float4*)(W + (size_t)(k0 + kB) * 512 + n0 + gB * 4);
        Bs[kB][gB*4+0] = wv.x; Bs[kB][gB*4+1] = wv.y;
        Bs[kB][gB*4+2] = wv.z; Bs[kB][gB*4+3] = wv.w;
        __syncthreads();
        #pragma unroll
        for (int kk = 0; kk < 16; kk++) {
            float a[8], b[4];
            #pragma unroll
            for (int i = 0; i < 8; i++) a[i] = As[kk][ty * 8 + i];
            #pragma unroll
            for (int j = 0; j < 4; j++) b[j] = Bs[kk][tx * 4 + j];
            #pragma unroll
            for (int i = 0; i < 8; i++)
                #pragma unroll
                for (int j = 0; j < 4; j++)
                    acc[i][j] += a[i] * b[j];
        }
        __syncthreads();
    }
    float b0 = bias[n0 + tx*4 + 0], b1 = bias[n0 + tx*4 + 1];
    float b2 = bias[n0 + tx*4 + 2], b3 = bias[n0 + tx*4 + 3];
    #pragma unroll
    for (int i = 0; i < 8; i++) {
        float4 o = make_float4(acc[i][0] + b0, acc[i][1] + b1,
                               acc[i][2] + b2, acc[i][3] + b3);
        *(float4*)(C + (size_t)(m0 + ty*8 + i) * 512 + n0 + tx*4) = o;
    }
}

// ---------------------------------------------------------------------------
// Scores, 64x64 tile, full tile staged once in dynamic smem (verified R7).
// ---------------------------------------------------------------------------
#define QS_OFF 0
#define KS_OFF (64*68)
#define ES_OFF (2*64*68)
#define SC_SMEM ((2*64*68 + 64*132) * 4)   // 68608 bytes

__global__ __launch_bounds__(256)
void scores_kernel(const float* __restrict__ E, float* __restrict__ attn)
{
    extern __shared__ float sm[];
    float* Qs = sm + QS_OFF;    // [dd][m]  stride 68
    float* Ks = sm + KS_OFF;    // [dd][m]  stride 68
    float* Es = sm + ES_OFF;    // [dd][ro] stride 132

    int idx = blockIdx.x;
    int qt = (int)((sqrtf(8.f * idx + 1.f) - 1.f) * 0.5f);
    while ((qt + 1) * (qt + 2) / 2 <= idx) qt++;
    while (qt * (qt + 1) / 2 > idx) qt--;
    int kt = idx - qt * (qt + 1) / 2;

    int bh = blockIdx.y;
    int b = bh >> 3, h = bh & 7;
    int q0 = qt * 64, k0 = kt * 64;

    int tid = threadIdx.x;
    int tx = tid & 15, ty = tid >> 4;

    const float* qbase = g_qp + (size_t)b * L_ * 512 + h * 64;
    const float* kbase = g_kp + (size_t)b * L_ * 512 + h * 64;
    int rbase = k0 - q0 + 1856;          // verified in R2/R3

    #pragma unroll
    for (int r = 0; r < 4; r++) {
        int u = tid + r * 256;
        int m = u >> 4, g = u & 15;
        float4 qv = *(const float4*)(qbase + (size_t)(q0 + m) * 512 + g * 4);
        Qs[(g*4+0)*68 + m] = qv.x; Qs[(g*4+1)*68 + m] = qv.y;
        Qs[(g*4+2)*68 + m] = qv.z; Qs[(g*4+3)*68 + m] = qv.w;
        float4 kv = *(const float4*)(kbase + (size_t)(k0 + m) * 512 + g * 4);
        Ks[(g*4+0)*68 + m] = kv.x; Ks[(g*4+1)*68 + m] = kv.y;
        Ks[(g*4+2)*68 + m] = kv.z; Ks[(g*4+3)*68 + m] = kv.w;
    }
    #pragma unroll
    for (int r = 0; r < 8; r++) {
        int u = tid + r * 256;
        if (u < 127 * 16) {
            int ro = u >> 4, g = u & 15;
            int rr = rbase + ro;
            float4 ev = make_float4(0.f, 0.f, 0.f, 0.f);
            if (rr >= 0 && rr < L_)
                ev = *(const float4*)(E + (size_t)(rr + 1) * 512 + h * 64 + g * 4);
            Es[(g*4+0)*132 + ro] = ev.x; Es[(g*4+1)*132 + ro] = ev.y;
            Es[(g*4+2)*132 + ro] = ev.z; Es[(g*4+3)*132 + ro] = ev.w;
        }
    }
    __syncthreads();

    float acc[4][4] = {};
    int ebase = 4 * (tx - ty) + 60;
    #pragma unroll 16
    for (int dd = 0; dd < 64; dd++) {
        float a[4], kv[4], ev[7];
        #pragma unroll
        for (int i = 0; i < 4; i++) a[i] = Qs[dd*68 + ty*4 + i];
        #pragma unroll
        for (int j = 0; j < 4; j++) kv[j] = Ks[dd*68 + tx*4 + j];
        #pragma unroll
        for (int t = 0; t < 7; t++) ev[t] = Es[dd*132 + ebase + t];
        #pragma unroll
        for (int i = 0; i < 4; i++)
            #pragma unroll
            for (int j = 0; j < 4; j++)
                acc[i][j] += a[i] * (kv[j] + ev[j - i + 3]);
    }

    bool diag = (qt == kt);
    float* out = attn + ((size_t)bh * L_ + q0) * L_ + k0;
    #pragma unroll
    for (int i = 0; i < 4; i++) {
        float v[4];
        #pragma unroll
        for (int j = 0; j < 4; j++) v[j] = acc[i][j] * 0.125f;
        *(float4*)(out + (size_t)(ty*4 + i) * L_ + tx*4) =
            make_float4(v[0], v[1], v[2], v[3]);

        int row = ty * 4 + i;
        float m = -1e30f;
        #pragma unroll
        for (int j = 0; j < 4; j++) {
            bool valid = !diag || (tx * 4 + j <= row);
            if (valid) m = fmaxf(m, v[j]);
        }
        #pragma unroll
        for (int off = 8; off > 0; off >>= 1)
            m = fmaxf(m, __shfl_xor_sync(0xffffffffu, m, off, 16));
        float s = 0.f;
        #pragma unroll
        for (int j = 0; j < 4; j++) {
            bool valid = !diag || (tx * 4 + j <= row);
            if (valid) s += __expf(v[j] - m);
        }
        #pragma unroll
        for (int off = 8; off > 0; off >>= 1)
            s += __shfl_xor_sync(0xffffffffu, s, off, 16);
        if (tx == 0)
            g_stats[((size_t)bh * NT_ + kt) * L_ + q0 + row] = make_float2(m, s);
    }
}

// ---------------------------------------------------------------------------
// Combine per-tile stats into per-row (max, 1/sum).
// ---------------------------------------------------------------------------
__global__ __launch_bounds__(256)
void statcomb_kernel()
{
    int p = blockIdx.x * 256 + threadIdx.x;
    if (p >= BH_ * L_) return;
    int bh = p / L_, q = p - bh * L_;
    int nt = q / 64 + 1;

    const float2* st = g_stats + (size_t)bh * NT_ * L_ + q;
    float M = -1e30f;
    for (int t = 0; t < nt; t++) M = fmaxf(M, st[(size_t)t * L_].x);
    float S = 0.f;
    for (int t = 0; t < nt; t++) {
        float2 v = st[(size_t)t * L_];
        S += v.y * __expf(v.x - M);
    }
    g_M[p] = M;
    g_I[p] = 1.f / S;
}

// ---------------------------------------------------------------------------
// Fused normalize + AV (split-K) + zerofill. Tile 128q x 64dh, micro 8x4.
// ---------------------------------------------------------------------------
__global__ __launch_bounds__(256)
void av_kernel(float* __restrict__ attn)
{
    int qt = blockIdx.x;                  // 0..14 (128-row tiles)
    int bh = blockIdx.y;
    int s  = blockIdx.z;
    int b = bh >> 3, h = bh & 7;
    int q0 = qt * 128;
    int tid = threadIdx.x;

    int kbeg = s * SPLITW;
    int kend = min(q0 + 128, kbeg + SPLITW);

    float* arow = attn + ((size_t)bh * L_ + q0) * L_;

    if (kbeg < kend) {
        __shared__ float As[16][132];
        __shared__ float Bs[16][68];
        __shared__ float sM[128];
        __shared__ float sI[128];
        int tx = tid & 15, ty = tid >> 4;
        float acc[8][4] = {};

        if (tid < 128) {
            sM[tid] = g_M[(size_t)bh * L_ + q0 + tid];
            sI[tid] = g_I[(size_t)bh * L_ + q0 + tid];
        }
        __syncthreads();

        const float* vbase = g_vp + (size_t)b * L_ * 512 + h * 64;
        int mA = tid >> 2, gA = tid & 3;
        int kB = tid >> 4, gB = tid & 15;
        float M0 = sM[mA],      I0 = sI[mA];
        float M1 = sM[64 + mA], I1 = sI[64 + mA];
        int qrow0 = q0 + mA, qrow1 = q0 + 64 + mA;

        for (int k0 = kbeg; k0 < kend; k0 += 16) {
            int kb = k0 + gA * 4;
            {
                float4 xv = *(float4*)(arow + (size_t)mA * L_ + kb);
                float4 p;
                p.x = (kb + 0 <= qrow0) ? __expf(xv.x - M0) * I0 : 0.f;
                p.y = (kb + 1 <= qrow0) ? __expf(xv.y - M0) * I0 : 0.f;
                p.z = (kb + 2 <= qrow0) ? __expf(xv.z - M0) * I0 : 0.f;
                p.w = (kb + 3 <= qrow0) ? __expf(xv.w - M0) * I0 : 0.f;
                *(float4*)(arow + (size_t)mA * L_ + kb) = p;
                As[gA*4+0][mA] = p.x; As[gA*4+1][mA] = p.y;
                As[gA*4+2][mA] = p.z; As[gA*4+3][mA] = p.w;
            }
            {
                float4 xv = *(float4*)(arow + (size_t)(64 + mA) * L_ + kb);
                float4 p;
                p.x = (kb + 0 <= qrow1) ? __expf(xv.x - M1) * I1 : 0.f;
                p.y = (kb + 1 <= qrow1) ? __expf(xv.y - M1) * I1 : 0.f;
                p.z = (kb + 2 <= qrow1) ? __expf(xv.z - M1) * I1 : 0.f;
                p.w = (kb + 3 <= qrow1) ? __expf(xv.w - M1) * I1 : 0.f;
                *(float4*)(arow + (size_t)(64 + mA) * L_ + kb) = p;
                As[gA*4+0][64+mA] = p.x; As[gA*4+1][64+mA] = p.y;
                As[gA*4+2][64+mA] = p.z; As[gA*4+3][64+mA] = p.w;
            }
            float4 vv = *(const float4*)(vbase + (size_t)(k0 + kB) * 512 + gB * 4);
            Bs[kB][gB*4+0] = vv.x; Bs[kB][gB*4+1] = vv.y;
            Bs[kB][gB*4+2] = vv.z; Bs[kB][gB*4+3] = vv.w;
            __syncthreads();
            #pragma unroll
            for (int kk = 0; kk < 16; kk++) {
                float a[8], bv[4];
                #pragma unroll
                for (int i = 0; i < 8; i++) a[i] = As[kk][ty * 8 + i];
                #pragma unroll
                for (int j = 0; j < 4; j++) bv[j] = Bs[kk][tx * 4 + j];
                #pragma unroll
                for (int i = 0; i < 8; i++)
                    #pragma unroll
                    for (int j = 0; j < 4; j++)
                        acc[i][j] += a[i] * bv[j];
            }
            __syncthreads();
        }

        float* op = g_op + (size_t)s * (BH_*L_*DH_) + ((size_t)bh * L_ + q0) * 64;
        #pragma unroll
        for (int i = 0; i < 8; i++) {
            float4 o = make_float4(acc[i][0], acc[i][1], acc[i][2], acc[i][3]);
            *(float4*)(op + (size_t)(ty*8 + i) * 64 + tx*4) = o;
        }
    }

    // zero-fill this split's strictly-non-causal columns for these 128 rows
    int zs = max(kbeg, q0 + 128) >> 2;
    int ze = min(kbeg + SPLITW, L_) >> 2;
    if (zs < ze) {
        float4 z = make_float4(0.f, 0.f, 0.f, 0.f);
        int row = tid >> 1;               // 128 rows, 2 threads per row
        float4* rp = (float4*)(arow + (size_t)row * L_);
        for (int c4 = zs + (tid & 1); c4 < ze; c4 += 2) rp[c4] = z;
    }
}

// ---------------------------------------------------------------------------
// out = (sum_s O_partial gathered across heads) @ Wo + bo.
// Tile 128x64, micro 8x4.
// ---------------------------------------------------------------------------
__global__ __launch_bounds__(256)
void oproj_kernel(const float* __restrict__ Wo, const float* __restrict__ bo,
                  float* __restrict__ out)
{
    __shared__ float As[16][132];
    __shared__ float Bs[16][68];
    int tid = threadIdx.x;
    int tx = tid & 15, ty = tid >> 4;
    int m0 = blockIdx.y * 128, n0 = blockIdx.x * 64;
    int b = m0 / L_;                      // 128 divides 1920: no straddle
    int l0 = m0 - b * L_;
    float acc[8][4] = {};

    int ns = (l0 + 128 + SPLITW - 1) / SPLITW;
    int mA = tid >> 2, gA = tid & 3;
    int kB = tid >> 4, gB = tid & 15;

    for (int k0 = 0; k0 < 512; k0 += 16) {
        int h = k0 >> 6, dh0 = k0 & 63;
        #pragma unroll
        for (int half = 0; half < 2; half++) {
            int m = half * 64 + mA;
            const float* base = g_op + (((size_t)(b*8 + h) * L_ + l0 + m) * 64 + dh0 + gA*4);
            float4 a4 = *(const float4*)(base);
            for (int ss = 1; ss < ns; ss++) {
                float4 t = *(const float4*)(base + (size_t)ss * (BH_*L_*DH_));
                a4.x += t.x; a4.y += t.y; a4.z += t.z; a4.w += t.w;
            }
            As[gA*4+0][m] = a4.x; As[gA*4+1][m] = a4.y;
            As[gA*4+2][m] = a4.z; As[gA*4+3][m] = a4.w;
        }
        float4 wv = *(const float4*)(Wo + (size_t)(k0 + kB) * 512 + n0 + gB * 4);
        Bs[kB][gB*4+0] = wv.x; Bs[kB][gB*4+1] = wv.y;
        Bs[kB][gB*4+2] = wv.z; Bs[kB][gB*4+3] = wv.w;
        __syncthreads();
        #pragma unroll
        for (int kk = 0; kk < 16; kk++) {
            float a[8], bv[4];
            #pragma unroll
            for (int i = 0; i < 8; i++) a[i] = As[kk][ty * 8 + i];
            #pragma unroll
            for (int j = 0; j < 4; j++) bv[j] = Bs[kk][tx * 4 + j];
            #pragma unroll
            for (int i = 0; i < 8; i++)
                #pragma unroll
                for (int j = 0; j < 4; j++)
                    acc[i][j] += a[i] * bv[j];
        }
        __syncthreads();
    }
    float b0 = bo[n0 + tx*4 + 0], b1 = bo[n0 + tx*4 + 1];
    float b2 = bo[n0 + tx*4 + 2], b3 = bo[n0 + tx*4 + 3];
    #pragma unroll
    for (int i = 0; i < 8; i++) {
        float4 o = make_float4(acc[i][0] + b0, acc[i][1] + b1,
                               acc[i][2] + b2, acc[i][3] + b3);
        *(float4*)(out + (size_t)(m0 + ty*8 + i) * 512 + n0 + tx*4) = o;
    }
}

// ---------------------------------------------------------------------------
extern "C" void kernel_launch(void* const* d_in, const int* in_sizes, int n_in,
                              void* d_out, int out_size)
{
    const float* q  = (const float*)d_in[0];
    const float* k  = (const float*)d_in[1];
    const float* v  = (const float*)d_in[2];
    const float* Wq = (const float*)d_in[4];
    const float* bq = (const float*)d_in[5];
    const float* Wk = (const float*)d_in[6];
    const float* bk = (const float*)d_in[7];
    const float* Wv = (const float*)d_in[8];
    const float* bv = (const float*)d_in[9];
    const float* E  = (const float*)d_in[10];
    const float* Wo = (const float*)d_in[11];
    const float* bo = (const float*)d_in[12];

    float* out_ptr  = (float*)d_out;
    float* attn_ptr = out_ptr + OUT_ELEMS;   // tuple order: (out, attn)

    cudaFuncSetAttribute(scores_kernel,
                         cudaFuncAttributeMaxDynamicSharedMemorySize, SC_SMEM);

    qkv_proj_kernel<<<dim3(8, 30, 3), 256>>>(q, k, v, Wq, Wk, Wv, bq, bk, bv);
    scores_kernel<<<dim3(465, 16), 256, SC_SMEM>>>(E, attn_ptr);
    statcomb_kernel<<<(BH_ * L_ + 255) / 256, 256>>>();
    av_kernel<<<dim3(15, 16, NSPLIT), 256>>>(attn_ptr);
    oproj_kernel<<<dim3(8, 30), 256>>>(Wo, bo, out_ptr);
}

// round 9
// speedup vs baseline: 1.3089x; 1.0096x over previous
#include <cuda_runtime.h>
#include <cuda_bf16.h>
#include <cstddef>

#define B_ 2
#define L_ 1920
#define D_ 512
#define H_ 8
#define DH_ 64
#define BH_ (B_*H_)
#define NT_ 30
#define OUT_ELEMS (B_*L_*D_)
#define NSPLIT 4
#define SPLITW 480

// Scratch (device globals; no cudaMalloc allowed)
__device__ float g_qp[B_*L_*D_];
__device__ float g_kp[B_*L_*D_];
__device__ float g_vp[B_*L_*D_];
__device__ float g_op[NSPLIT * BH_*L_*DH_];
__device__ float2 g_stats[BH_*NT_*L_];     // per (bh,kt,q): tile max, tile sumexp
__device__ float  g_F[BH_*NT_*L_];         // per (bh,kt,q): exp(m-M)*invS

// ---------------------------------------------------------------------------
// QKV projection. Tile 128x64, 256 thr, micro 8x4.
// ---------------------------------------------------------------------------
__global__ __launch_bounds__(256)
void qkv_proj_kernel(const float* __restrict__ q, const float* __restrict__ k,
                     const float* __restrict__ v,
                     const float* __restrict__ Wq, const float* __restrict__ Wk,
                     const float* __restrict__ Wv,
                     const float* __restrict__ bq, const float* __restrict__ bk,
                     const float* __restrict__ bv)
{
    const float* A; const float* W; const float* bias; float* C;
    int z = blockIdx.z;
    if (z == 0)      { A = q; W = Wq; bias = bq; C = g_qp; }
    else if (z == 1) { A = k; W = Wk; bias = bk; C = g_kp; }
    else             { A = v; W = Wv; bias = bv; C = g_vp; }

    __shared__ float As[16][132];
    __shared__ float Bs[16][68];
    int tid = threadIdx.x;
    int tx = tid & 15, ty = tid >> 4;
    int m0 = blockIdx.y * 128, n0 = blockIdx.x * 64;
    float acc[8][4] = {};

    int mA = tid >> 2, gA = tid & 3;
    int kB = tid >> 4, gB = tid & 15;

    for (int k0 = 0; k0 < 512; k0 += 16) {
        float4 a0 = *(const float4*)(A + (size_t)(m0 + mA) * 512 + k0 + gA * 4);
        As[gA*4+0][mA] = a0.x; As[gA*4+1][mA] = a0.y;
        As[gA*4+2][mA] = a0.z; As[gA*4+3][mA] = a0.w;
        float4 a1 = *(const float4*)(A + (size_t)(m0 + 64 + mA) * 512 + k0 + gA * 4);
        As[gA*4+0][64+mA] = a1.x; As[gA*4+1][64+mA] = a1.y;
        As[gA*4+2][64+mA] = a1.z; As[gA*4+3][64+mA] = a1.w;
        float4 wv = *(const float4*)(W + (size_t)(k0 + kB) * 512 + n0 + gB * 4);
        Bs[kB][gB*4+0] = wv.x; Bs[kB][gB*4+1] = wv.y;
        Bs[kB][gB*4+2] = wv.z; Bs[kB][gB*4+3] = wv.w;
        __syncthreads();
        #pragma unroll
        for (int kk = 0; kk < 16; kk++) {
            float a[8], b[4];
            #pragma unroll
            for (int i = 0; i < 8; i++) a[i] = As[kk][ty * 8 + i];
            #pragma unroll
            for (int j = 0; j < 4; j++) b[j] = Bs[kk][tx * 4 + j];
            #pragma unroll
            for (int i = 0; i < 8; i++)
                #pragma unroll
                for (int j = 0; j < 4; j++)
                    acc[i][j] += a[i] * b[j];
        }
        __syncthreads();
    }
    float b0 = bias[n0 + tx*4 + 0], b1 = bias[n0 + tx*4 + 1];
    float b2 = bias[n0 + tx*4 + 2], b3 = bias[n0 + tx*4 + 3];
    #pragma unroll
    for (int i = 0; i < 8; i++) {
        float4 o = make_float4(acc[i][0] + b0, acc[i][1] + b1,
                               acc[i][2] + b2, acc[i][3] + b3);
        *(float4*)(C + (size_t)(m0 + ty*8 + i) * 512 + n0 + tx*4) = o;
    }
}

// ---------------------------------------------------------------------------
// Scores, 64x64 tile, full tile staged once in dynamic smem (verified R7/R8).
// NEW: stores p~ = exp(logit - m_tile) into attn (exp computed once here),
// plus per-(row,ktile) stats (m, sum).
// ---------------------------------------------------------------------------
#define QS_OFF 0
#define KS_OFF (64*68)
#define ES_OFF (2*64*68)
#define SC_SMEM ((2*64*68 + 64*132) * 4)   // 68608 bytes

__global__ __launch_bounds__(256)
void scores_kernel(const float* __restrict__ E, float* __restrict__ attn)
{
    extern __shared__ float sm[];
    float* Qs = sm + QS_OFF;
    float* Ks = sm + KS_OFF;
    float* Es = sm + ES_OFF;

    int idx = blockIdx.x;
    int qt = (int)((sqrtf(8.f * idx + 1.f) - 1.f) * 0.5f);
    while ((qt + 1) * (qt + 2) / 2 <= idx) qt++;
    while (qt * (qt + 1) / 2 > idx) qt--;
    int kt = idx - qt * (qt + 1) / 2;

    int bh = blockIdx.y;
    int b = bh >> 3, h = bh & 7;
    int q0 = qt * 64, k0 = kt * 64;

    int tid = threadIdx.x;
    int tx = tid & 15, ty = tid >> 4;

    const float* qbase = g_qp + (size_t)b * L_ * 512 + h * 64;
    const float* kbase = g_kp + (size_t)b * L_ * 512 + h * 64;
    int rbase = k0 - q0 + 1856;          // verified in R2/R3

    #pragma unroll
    for (int r = 0; r < 4; r++) {
        int u = tid + r * 256;
        int m = u >> 4, g = u & 15;
        float4 qv = *(const float4*)(qbase + (size_t)(q0 + m) * 512 + g * 4);
        Qs[(g*4+0)*68 + m] = qv.x; Qs[(g*4+1)*68 + m] = qv.y;
        Qs[(g*4+2)*68 + m] = qv.z; Qs[(g*4+3)*68 + m] = qv.w;
        float4 kv = *(const float4*)(kbase + (size_t)(k0 + m) * 512 + g * 4);
        Ks[(g*4+0)*68 + m] = kv.x; Ks[(g*4+1)*68 + m] = kv.y;
        Ks[(g*4+2)*68 + m] = kv.z; Ks[(g*4+3)*68 + m] = kv.w;
    }
    #pragma unroll
    for (int r = 0; r < 8; r++) {
        int u = tid + r * 256;
        if (u < 127 * 16) {
            int ro = u >> 4, g = u & 15;
            int rr = rbase + ro;
            float4 ev = make_float4(0.f, 0.f, 0.f, 0.f);
            if (rr >= 0 && rr < L_)
                ev = *(const float4*)(E + (size_t)(rr + 1) * 512 + h * 64 + g * 4);
            Es[(g*4+0)*132 + ro] = ev.x; Es[(g*4+1)*132 + ro] = ev.y;
            Es[(g*4+2)*132 + ro] = ev.z; Es[(g*4+3)*132 + ro] = ev.w;
        }
    }
    __syncthreads();

    float acc[4][4] = {};
    int ebase = 4 * (tx - ty) + 60;
    #pragma unroll 16
    for (int dd = 0; dd < 64; dd++) {
        float a[4], kv[4], ev[7];
        #pragma unroll
        for (int i = 0; i < 4; i++) a[i] = Qs[dd*68 + ty*4 + i];
        #pragma unroll
        for (int j = 0; j < 4; j++) kv[j] = Ks[dd*68 + tx*4 + j];
        #pragma unroll
        for (int t = 0; t < 7; t++) ev[t] = Es[dd*132 + ebase + t];
        #pragma unroll
        for (int i = 0; i < 4; i++)
            #pragma unroll
            for (int j = 0; j < 4; j++)
                acc[i][j] += a[i] * (kv[j] + ev[j - i + 3]);
    }

    bool diag = (qt == kt);
    float* out = attn + ((size_t)bh * L_ + q0) * L_ + k0;
    #pragma unroll
    for (int i = 0; i < 4; i++) {
        float v[4];
        #pragma unroll
        for (int j = 0; j < 4; j++) v[j] = acc[i][j] * 0.125f;

        int row = ty * 4 + i;
        // masked row max over the 16 tx lanes
        float m = -1e30f;
        #pragma unroll
        for (int j = 0; j < 4; j++) {
            bool valid = !diag || (tx * 4 + j <= row);
            if (valid) m = fmaxf(m, v[j]);
        }
        #pragma unroll
        for (int off = 8; off > 0; off >>= 1)
            m = fmaxf(m, __shfl_xor_sync(0xffffffffu, m, off, 16));

        // p~ = exp(v - m): the ONLY exp over the attn matrix in the pipeline
        float e[4];
        #pragma unroll
        for (int j = 0; j < 4; j++) e[j] = __expf(v[j] - m);
        *(float4*)(out + (size_t)row * L_ + tx*4) =
            make_float4(e[0], e[1], e[2], e[3]);

        float s = 0.f;
        #pragma unroll
        for (int j = 0; j < 4; j++) {
            bool valid = !diag || (tx * 4 + j <= row);
            if (valid) s += e[j];
        }
        #pragma unroll
        for (int off = 8; off > 0; off >>= 1)
            s += __shfl_xor_sync(0xffffffffu, s, off, 16);
        if (tx == 0)
            g_stats[((size_t)bh * NT_ + kt) * L_ + q0 + row] = make_float2(m, s);
    }
}

// ---------------------------------------------------------------------------
// Combine per-tile stats; emit per-(row,ktile) rescale F = exp(m-M)*invS.
// ---------------------------------------------------------------------------
__global__ __launch_bounds__(256)
void statcomb_kernel()
{
    int p = blockIdx.x * 256 + threadIdx.x;
    if (p >= BH_ * L_) return;
    int bh = p / L_, q = p - bh * L_;
    int nt = q / 64 + 1;

    const float2* st = g_stats + (size_t)bh * NT_ * L_ + q;
    float M = -1e30f;
    for (int t = 0; t < nt; t++) M = fmaxf(M, st[(size_t)t * L_].x);
    float S = 0.f;
    for (int t = 0; t < nt; t++) {
        float2 v = st[(size_t)t * L_];
        S += v.y * __expf(v.x - M);
    }
    float I = 1.f / S;
    float* F = g_F + (size_t)bh * NT_ * L_ + q;
    for (int t = 0; t < nt; t++)
        F[(size_t)t * L_] = __expf(st[(size_t)t * L_].x - M) * I;
}

// ---------------------------------------------------------------------------
// Fused normalize + AV (split-K) + zerofill. Tile 128q x 64dh, micro 8x4.
// exp-free: p = p~ * F[row, ktile]  (masked 0 above the diagonal).
// ---------------------------------------------------------------------------
__global__ __launch_bounds__(256)
void av_kernel(float* __restrict__ attn)
{
    int qt = blockIdx.x;                  // 128-row tiles
    int bh = blockIdx.y;
    int s  = blockIdx.z;
    int b = bh >> 3, h = bh & 7;
    int q0 = qt * 128;
    int tid = threadIdx.x;

    int kbeg = s * SPLITW;
    int kend = min(q0 + 128, kbeg + SPLITW);

    float* arow = attn + ((size_t)bh * L_ + q0) * L_;

    if (kbeg < kend) {
        __shared__ float As[16][132];
        __shared__ float Bs[16][68];
        int tx = tid & 15, ty = tid >> 4;
        float acc[8][4] = {};

        const float* vbase = g_vp + (size_t)b * L_ * 512 + h * 64;
        const float* Fb = g_F + (size_t)bh * NT_ * L_;
        int mA = tid >> 2, gA = tid & 3;
        int kB = tid >> 4, gB = tid & 15;
        int qrow0 = q0 + mA, qrow1 = q0 + 64 + mA;

        for (int k0 = kbeg; k0 < kend; k0 += 16) {
            int kb = k0 + gA * 4;
            int kt = k0 >> 6;
            float F0 = Fb[(size_t)kt * L_ + qrow0];
            float F1 = Fb[(size_t)kt * L_ + qrow1];
            {
                float4 xv = *(float4*)(arow + (size_t)mA * L_ + kb);
                float4 p;
                p.x = (kb + 0 <= qrow0) ? xv.x * F0 : 0.f;
                p.y = (kb + 1 <= qrow0) ? xv.y * F0 : 0.f;
                p.z = (kb + 2 <= qrow0) ? xv.z * F0 : 0.f;
                p.w = (kb + 3 <= qrow0) ? xv.w * F0 : 0.f;
                *(float4*)(arow + (size_t)mA * L_ + kb) = p;
                As[gA*4+0][mA] = p.x; As[gA*4+1][mA] = p.y;
                As[gA*4+2][mA] = p.z; As[gA*4+3][mA] = p.w;
            }
            {
                float4 xv = *(float4*)(arow + (size_t)(64 + mA) * L_ + kb);
                float4 p;
                p.x = (kb + 0 <= qrow1) ? xv.x * F1 : 0.f;
                p.y = (kb + 1 <= qrow1) ? xv.y * F1 : 0.f;
                p.z = (kb + 2 <= qrow1) ? xv.z * F1 : 0.f;
                p.w = (kb + 3 <= qrow1) ? xv.w * F1 : 0.f;
                *(float4*)(arow + (size_t)(64 + mA) * L_ + kb) = p;
                As[gA*4+0][64+mA] = p.x; As[gA*4+1][64+mA] = p.y;
                As[gA*4+2][64+mA] = p.z; As[gA*4+3][64+mA] = p.w;
            }
            float4 vv = *(const float4*)(vbase + (size_t)(k0 + kB) * 512 + gB * 4);
            Bs[kB][gB*4+0] = vv.x; Bs[kB][gB*4+1] = vv.y;
            Bs[kB][gB*4+2] = vv.z; Bs[kB][gB*4+3] = vv.w;
            __syncthreads();
            #pragma unroll
            for (int kk = 0; kk < 16; kk++) {
                float a[8], bv[4];
                #pragma unroll
                for (int i = 0; i < 8; i++) a[i] = As[kk][ty * 8 + i];
                #pragma unroll
                for (int j = 0; j < 4; j++) bv[j] = Bs[kk][tx * 4 + j];
                #pragma unroll
                for (int i = 0; i < 8; i++)
                    #pragma unroll
                    for (int j = 0; j < 4; j++)
                        acc[i][j] += a[i] * bv[j];
            }
            __syncthreads();
        }

        float* op = g_op + (size_t)s * (BH_*L_*DH_) + ((size_t)bh * L_ + q0) * 64;
        #pragma unroll
        for (int i = 0; i < 8; i++) {
            float4 o = make_float4(acc[i][0], acc[i][1], acc[i][2], acc[i][3]);
            *(float4*)(op + (size_t)(ty*8 + i) * 64 + tx*4) = o;
        }
    }

    // zero-fill this split's strictly-non-causal columns for these 128 rows
    int zs = max(kbeg, q0 + 128) >> 2;
    int ze = min(kbeg + SPLITW, L_) >> 2;
    if (zs < ze) {
        float4 z = make_float4(0.f, 0.f, 0.f, 0.f);
        int row = tid >> 1;
        float4* rp = (float4*)(arow + (size_t)row * L_);
        for (int c4 = zs + (tid & 1); c4 < ze; c4 += 2) rp[c4] = z;
    }
}

// ---------------------------------------------------------------------------
// out = (sum_s O_partial gathered across heads) @ Wo + bo. Tile 128x64.
// ---------------------------------------------------------------------------
__global__ __launch_bounds__(256)
void oproj_kernel(const float* __restrict__ Wo, const float* __restrict__ bo,
                  float* __restrict__ out)
{
    __shared__ float As[16][132];
    __shared__ float Bs[16][68];
    int tid = threadIdx.x;
    int tx = tid & 15, ty = tid >> 4;
    int m0 = blockIdx.y * 128, n0 = blockIdx.x * 64;
    int b = m0 / L_;
    int l0 = m0 - b * L_;
    float acc[8][4] = {};

    int ns = (l0 + 128 + SPLITW - 1) / SPLITW;
    int mA = tid >> 2, gA = tid & 3;
    int kB = tid >> 4, gB = tid & 15;

    for (int k0 = 0; k0 < 512; k0 += 16) {
        int h = k0 >> 6, dh0 = k0 & 63;
        #pragma unroll
        for (int half = 0; half < 2; half++) {
            int m = half * 64 + mA;
            const float* base = g_op + (((size_t)(b*8 + h) * L_ + l0 + m) * 64 + dh0 + gA*4);
            float4 a4 = *(const float4*)(base);
            for (int ss = 1; ss < ns; ss++) {
                float4 t = *(const float4*)(base + (size_t)ss * (BH_*L_*DH_));
                a4.x += t.x; a4.y += t.y; a4.z += t.z; a4.w += t.w;
            }
            As[gA*4+0][m] = a4.x; As[gA*4+1][m] = a4.y;
            As[gA*4+2][m] = a4.z; As[gA*4+3][m] = a4.w;
        }
        float4 wv = *(const float4*)(Wo + (size_t)(k0 + kB) * 512 + n0 + gB * 4);
        Bs[kB][gB*4+0] = wv.x; Bs[kB][gB*4+1] = wv.y;
        Bs[kB][gB*4+2] = wv.z; Bs[kB][gB*4+3] = wv.w;
        __syncthreads();
        #pragma unroll
        for (int kk = 0; kk < 16; kk++) {
            float a[8], bv[4];
            #pragma unroll
            for (int i = 0; i < 8; i++) a[i] = As[kk][ty * 8 + i];
            #pragma unroll
            for (int j = 0; j < 4; j++) bv[j] = Bs[kk][tx * 4 + j];
            #pragma unroll
            for (int i = 0; i < 8; i++)
                #pragma unroll
                for (int j = 0; j < 4; j++)
                    acc[i][j] += a[i] * bv[j];
        }
        __syncthreads();
    }
    float b0 = bo[n0 + tx*4 + 0], b1 = bo[n0 + tx*4 + 1];
    float b2 = bo[n0 + tx*4 + 2], b3 = bo[n0 + tx*4 + 3];
    #pragma unroll
    for (int i = 0; i < 8; i++) {
        float4 o = make_float4(acc[i][0] + b0, acc[i][1] + b1,
                               acc[i][2] + b2, acc[i][3] + b3);
        *(float4*)(out + (size_t)(m0 + ty*8 + i) * 512 + n0 + tx*4) = o;
    }
}

// ---------------------------------------------------------------------------
extern "C" void kernel_launch(void* const* d_in, const int* in_sizes, int n_in,
                              void* d_out, int out_size)
{
    const float* q  = (const float*)d_in[0];
    const float* k  = (const float*)d_in[1];
    const float* v  = (const float*)d_in[2];
    const float* Wq = (const float*)d_in[4];
    const float* bq = (const float*)d_in[5];
    const float* Wk = (const float*)d_in[6];
    const float* bk = (const float*)d_in[7];
    const float* Wv = (const float*)d_in[8];
    const float* bv = (const float*)d_in[9];
    const float* E  = (const float*)d_in[10];
    const float* Wo = (const float*)d_in[11];
    const float* bo = (const float*)d_in[12];

    float* out_ptr  = (float*)d_out;
    float* attn_ptr = out_ptr + OUT_ELEMS;   // tuple order: (out, attn)

    cudaFuncSetAttribute(scores_kernel,
                         cudaFuncAttributeMaxDynamicSharedMemorySize, SC_SMEM);

    qkv_proj_kernel<<<dim3(8, 30, 3), 256>>>(q, k, v, Wq, Wk, Wv, bq, bk, bv);
    scores_kernel<<<dim3(465, 16), 256, SC_SMEM>>>(E, attn_ptr);
    statcomb_kernel<<<(BH_ * L_ + 255) / 256, 256>>>();
    av_kernel<<<dim3(15, 16, NSPLIT), 256>>>(attn_ptr);
    oproj_kernel<<<dim3(8, 30), 256>>>(Wo, bo, out_ptr);
}

// round 10
// speedup vs baseline: 1.4098x; 1.0771x over previous
#include <cuda_runtime.h>
#include <cuda_bf16.h>
#include <cstddef>

#define B_ 2
#define L_ 1920
#define D_ 512
#define H_ 8
#define DH_ 64
#define BH_ (B_*H_)
#define NT_ 30
#define OUT_ELEMS (B_*L_*D_)
#define NSPLIT 4
#define SPLITW 480

// Scratch (device globals; no cudaMalloc allowed)
__device__ float g_qp[B_*L_*D_];
__device__ float g_kp[B_*L_*D_];
__device__ float g_vp[B_*L_*D_];
__device__ float g_op[NSPLIT * BH_*L_*DH_];
__device__ float2 g_stats[BH_*NT_*L_];     // per (bh,kt,q): tile max, tile sumexp
__device__ float  g_F[BH_*NT_*L_];         // per (bh,kt,q): exp(m-M)*invS

// ---------------------------------------------------------------------------
// QKV projection. Tile 128x64, micro 8x4, register prefetch.
// ---------------------------------------------------------------------------
__global__ __launch_bounds__(256)
void qkv_proj_kernel(const float* __restrict__ q, const float* __restrict__ k,
                     const float* __restrict__ v,
                     const float* __restrict__ Wq, const float* __restrict__ Wk,
                     const float* __restrict__ Wv,
                     const float* __restrict__ bq, const float* __restrict__ bk,
                     const float* __restrict__ bv)
{
    const float* A; const float* W; const float* bias; float* C;
    int z = blockIdx.z;
    if (z == 0)      { A = q; W = Wq; bias = bq; C = g_qp; }
    else if (z == 1) { A = k; W = Wk; bias = bk; C = g_kp; }
    else             { A = v; W = Wv; bias = bv; C = g_vp; }

    __shared__ float As[16][132];
    __shared__ float Bs[16][68];
    int tid = threadIdx.x;
    int tx = tid & 15, ty = tid >> 4;
    int m0 = blockIdx.y * 128, n0 = blockIdx.x * 64;
    float acc[8][4] = {};

    int mA = tid >> 2, gA = tid & 3;
    int kB = tid >> 4, gB = tid & 15;

    float4 a0 = *(const float4*)(A + (size_t)(m0 + mA) * 512 + gA * 4);
    float4 a1 = *(const float4*)(A + (size_t)(m0 + 64 + mA) * 512 + gA * 4);
    float4 wv = *(const float4*)(W + (size_t)kB * 512 + n0 + gB * 4);

    for (int k0 = 0; k0 < 512; k0 += 16) {
        As[gA*4+0][mA] = a0.x; As[gA*4+1][mA] = a0.y;
        As[gA*4+2][mA] = a0.z; As[gA*4+3][mA] = a0.w;
        As[gA*4+0][64+mA] = a1.x; As[gA*4+1][64+mA] = a1.y;
        As[gA*4+2][64+mA] = a1.z; As[gA*4+3][64+mA] = a1.w;
        Bs[kB][gB*4+0] = wv.x; Bs[kB][gB*4+1] = wv.y;
        Bs[kB][gB*4+2] = wv.z; Bs[kB][gB*4+3] = wv.w;
        __syncthreads();
        if (k0 + 16 < 512) {   // prefetch next chunk; overlaps the mainloop
            a0 = *(const float4*)(A + (size_t)(m0 + mA) * 512 + k0 + 16 + gA * 4);
            a1 = *(const float4*)(A + (size_t)(m0 + 64 + mA) * 512 + k0 + 16 + gA * 4);
            wv = *(const float4*)(W + (size_t)(k0 + 16 + kB) * 512 + n0 + gB * 4);
        }
        #pragma unroll
        for (int kk = 0; kk < 16; kk++) {
            float a[8], b[4];
            #pragma unroll
            for (int i = 0; i < 8; i++) a[i] = As[kk][ty * 8 + i];
            #pragma unroll
            for (int j = 0; j < 4; j++) b[j] = Bs[kk][tx * 4 + j];
            #pragma unroll
            for (int i = 0; i < 8; i++)
                #pragma unroll
                for (int j = 0; j < 4; j++)
                    acc[i][j] += a[i] * b[j];
        }
        __syncthreads();
    }
    float b0 = bias[n0 + tx*4 + 0], b1 = bias[n0 + tx*4 + 1];
    float b2 = bias[n0 + tx*4 + 2], b3 = bias[n0 + tx*4 + 3];
    #pragma unroll
    for (int i = 0; i < 8; i++) {
        float4 o = make_float4(acc[i][0] + b0, acc[i][1] + b1,
                               acc[i][2] + b2, acc[i][3] + b3);
        *(float4*)(C + (size_t)(m0 + ty*8 + i) * 512 + n0 + tx*4) = o;
    }
}

// ---------------------------------------------------------------------------
// Scores, 64x64 tile, full tile staged once in dynamic smem (verified R9).
// Stores p~ = exp(logit - m_tile) into attn + per-(row,ktile) stats.
// ---------------------------------------------------------------------------
#define QS_OFF 0
#define KS_OFF (64*68)
#define ES_OFF (2*64*68)
#define SC_SMEM ((2*64*68 + 64*132) * 4)   // 68608 bytes

__global__ __launch_bounds__(256)
void scores_kernel(const float* __restrict__ E, float* __restrict__ attn)
{
    extern __shared__ float sm[];
    float* Qs = sm + QS_OFF;
    float* Ks = sm + KS_OFF;
    float* Es = sm + ES_OFF;

    int idx = blockIdx.x;
    int qt = (int)((sqrtf(8.f * idx + 1.f) - 1.f) * 0.5f);
    while ((qt + 1) * (qt + 2) / 2 <= idx) qt++;
    while (qt * (qt + 1) / 2 > idx) qt--;
    int kt = idx - qt * (qt + 1) / 2;

    int bh = blockIdx.y;
    int b = bh >> 3, h = bh & 7;
    int q0 = qt * 64, k0 = kt * 64;

    int tid = threadIdx.x;
    int tx = tid & 15, ty = tid >> 4;

    const float* qbase = g_qp + (size_t)b * L_ * 512 + h * 64;
    const float* kbase = g_kp + (size_t)b * L_ * 512 + h * 64;
    int rbase = k0 - q0 + 1856;          // verified in R2/R3

    #pragma unroll
    for (int r = 0; r < 4; r++) {
        int u = tid + r * 256;
        int m = u >> 4, g = u & 15;
        float4 qv = *(const float4*)(qbase + (size_t)(q0 + m) * 512 + g * 4);
        Qs[(g*4+0)*68 + m] = qv.x; Qs[(g*4+1)*68 + m] = qv.y;
        Qs[(g*4+2)*68 + m] = qv.z; Qs[(g*4+3)*68 + m] = qv.w;
        float4 kv = *(const float4*)(kbase + (size_t)(k0 + m) * 512 + g * 4);
        Ks[(g*4+0)*68 + m] = kv.x; Ks[(g*4+1)*68 + m] = kv.y;
        Ks[(g*4+2)*68 + m] = kv.z; Ks[(g*4+3)*68 + m] = kv.w;
    }
    #pragma unroll
    for (int r = 0; r < 8; r++) {
        int u = tid + r * 256;
        if (u < 127 * 16) {
            int ro = u >> 4, g = u & 15;
            int rr = rbase + ro;
            float4 ev = make_float4(0.f, 0.f, 0.f, 0.f);
            if (rr >= 0 && rr < L_)
                ev = *(const float4*)(E + (size_t)(rr + 1) * 512 + h * 64 + g * 4);
            Es[(g*4+0)*132 + ro] = ev.x; Es[(g*4+1)*132 + ro] = ev.y;
            Es[(g*4+2)*132 + ro] = ev.z; Es[(g*4+3)*132 + ro] = ev.w;
        }
    }
    __syncthreads();

    float acc[4][4] = {};
    int ebase = 4 * (tx - ty) + 60;
    #pragma unroll 16
    for (int dd = 0; dd < 64; dd++) {
        float a[4], kv[4], ev[7];
        #pragma unroll
        for (int i = 0; i < 4; i++) a[i] = Qs[dd*68 + ty*4 + i];
        #pragma unroll
        for (int j = 0; j < 4; j++) kv[j] = Ks[dd*68 + tx*4 + j];
        #pragma unroll
        for (int t = 0; t < 7; t++) ev[t] = Es[dd*132 + ebase + t];
        #pragma unroll
        for (int i = 0; i < 4; i++)
            #pragma unroll
            for (int j = 0; j < 4; j++)
                acc[i][j] += a[i] * (kv[j] + ev[j - i + 3]);
    }

    bool diag = (qt == kt);
    float* out = attn + ((size_t)bh * L_ + q0) * L_ + k0;
    #pragma unroll
    for (int i = 0; i < 4; i++) {
        float v[4];
        #pragma unroll
        for (int j = 0; j < 4; j++) v[j] = acc[i][j] * 0.125f;

        int row = ty * 4 + i;
        float m = -1e30f;
        #pragma unroll
        for (int j = 0; j < 4; j++) {
            bool valid = !diag || (tx * 4 + j <= row);
            if (valid) m = fmaxf(m, v[j]);
        }
        #pragma unroll
        for (int off = 8; off > 0; off >>= 1)
            m = fmaxf(m, __shfl_xor_sync(0xffffffffu, m, off, 16));

        float e[4];
        #pragma unroll
        for (int j = 0; j < 4; j++) e[j] = __expf(v[j] - m);
        *(float4*)(out + (size_t)row * L_ + tx*4) =
            make_float4(e[0], e[1], e[2], e[3]);

        float s = 0.f;
        #pragma unroll
        for (int j = 0; j < 4; j++) {
            bool valid = !diag || (tx * 4 + j <= row);
            if (valid) s += e[j];
        }
        #pragma unroll
        for (int off = 8; off > 0; off >>= 1)
            s += __shfl_xor_sync(0xffffffffu, s, off, 16);
        if (tx == 0)
            g_stats[((size_t)bh * NT_ + kt) * L_ + q0 + row] = make_float2(m, s);
    }
}

// ---------------------------------------------------------------------------
// Combine per-tile stats; emit per-(row,ktile) rescale F = exp(m-M)*invS.
// ---------------------------------------------------------------------------
__global__ __launch_bounds__(256)
void statcomb_kernel()
{
    int p = blockIdx.x * 256 + threadIdx.x;
    if (p >= BH_ * L_) return;
    int bh = p / L_, q = p - bh * L_;
    int nt = q / 64 + 1;

    const float2* st = g_stats + (size_t)bh * NT_ * L_ + q;
    float M = -1e30f;
    for (int t = 0; t < nt; t++) M = fmaxf(M, st[(size_t)t * L_].x);
    float S = 0.f;
    for (int t = 0; t < nt; t++) {
        float2 v = st[(size_t)t * L_];
        S += v.y * __expf(v.x - M);
    }
    float I = 1.f / S;
    float* F = g_F + (size_t)bh * NT_ * L_ + q;
    for (int t = 0; t < nt; t++)
        F[(size_t)t * L_] = __expf(st[(size_t)t * L_].x - M) * I;
}

// ---------------------------------------------------------------------------
// Fused normalize + AV (split-K) + zerofill. 64-row tiles, micro 4x4,
// register prefetch. exp-free: p = p~ * F[row, ktile].
// ---------------------------------------------------------------------------
__global__ __launch_bounds__(256)
void av_kernel(float* __restrict__ attn)
{
    int qt = blockIdx.x;                  // 64-row tiles (0..29)
    int bh = blockIdx.y;
    int s  = blockIdx.z;
    int b = bh >> 3, h = bh & 7;
    int q0 = qt * 64;
    int tid = threadIdx.x;

    int kbeg = s * SPLITW;
    int kend = min(q0 + 64, kbeg + SPLITW);

    float* arow = attn + ((size_t)bh * L_ + q0) * L_;

    if (kbeg < kend) {
        __shared__ float As[16][68];
        __shared__ float Bs[16][68];
        int tx = tid & 15, ty = tid >> 4;
        float acc[4][4] = {};

        const float* vbase = g_vp + (size_t)b * L_ * 512 + h * 64;
        const float* Fb = g_F + (size_t)bh * NT_ * L_;
        int mA = tid >> 2, gA = tid & 3;
        int kB = tid >> 4, gB = tid & 15;
        int qrow = q0 + mA;

        // prefetch first chunk
        float4 xv = *(float4*)(arow + (size_t)mA * L_ + kbeg + gA * 4);
        float4 vv = *(const float4*)(vbase + (size_t)(kbeg + kB) * 512 + gB * 4);
        float Fc = Fb[(size_t)(kbeg >> 6) * L_ + qrow];

        for (int k0 = kbeg; k0 < kend; k0 += 16) {
            int kb = k0 + gA * 4;
            float4 p;
            p.x = (kb + 0 <= qrow) ? xv.x * Fc : 0.f;
            p.y = (kb + 1 <= qrow) ? xv.y * Fc : 0.f;
            p.z = (kb + 2 <= qrow) ? xv.z * Fc : 0.f;
            p.w = (kb + 3 <= qrow) ? xv.w * Fc : 0.f;
            *(float4*)(arow + (size_t)mA * L_ + kb) = p;   // final attn value
            As[gA*4+0][mA] = p.x; As[gA*4+1][mA] = p.y;
            As[gA*4+2][mA] = p.z; As[gA*4+3][mA] = p.w;
            Bs[kB][gB*4+0] = vv.x; Bs[kB][gB*4+1] = vv.y;
            Bs[kB][gB*4+2] = vv.z; Bs[kB][gB*4+3] = vv.w;
            __syncthreads();
            if (k0 + 16 < kend) {   // prefetch next chunk; overlaps mainloop
                xv = *(float4*)(arow + (size_t)mA * L_ + k0 + 16 + gA * 4);
                vv = *(const float4*)(vbase + (size_t)(k0 + 16 + kB) * 512 + gB * 4);
                Fc = Fb[(size_t)((k0 + 16) >> 6) * L_ + qrow];
            }
            #pragma unroll
            for (int kk = 0; kk < 16; kk++) {
                float a[4], bv[4];
                #pragma unroll
                for (int i = 0; i < 4; i++) a[i] = As[kk][ty * 4 + i];
                #pragma unroll
                for (int j = 0; j < 4; j++) bv[j] = Bs[kk][tx * 4 + j];
                #pragma unroll
                for (int i = 0; i < 4; i++)
                    #pragma unroll
                    for (int j = 0; j < 4; j++)
                        acc[i][j] += a[i] * bv[j];
            }
            __syncthreads();
        }

        float* op = g_op + (size_t)s * (BH_*L_*DH_) + ((size_t)bh * L_ + q0) * 64;
        #pragma unroll
        for (int i = 0; i < 4; i++) {
            float4 o = make_float4(acc[i][0], acc[i][1], acc[i][2], acc[i][3]);
            *(float4*)(op + (size_t)(ty*4 + i) * 64 + tx*4) = o;
        }
    }

    // zero-fill this split's strictly-non-causal columns for these 64 rows
    int zs = max(kbeg, q0 + 64) >> 2;
    int ze = min(kbeg + SPLITW, L_) >> 2;
    if (zs < ze) {
        float4 z = make_float4(0.f, 0.f, 0.f, 0.f);
        int row = tid >> 2;               // 64 rows, 4 threads per row
        float4* rp = (float4*)(arow + (size_t)row * L_);
        for (int c4 = zs + (tid & 3); c4 < ze; c4 += 4) rp[c4] = z;
    }
}

// ---------------------------------------------------------------------------
// out = (sum_s O_partial gathered across heads) @ Wo + bo. Tile 128x64.
// Per-64-row-half split count (av tiles are 64 rows wide).
// ---------------------------------------------------------------------------
__global__ __launch_bounds__(256)
void oproj_kernel(const float* __restrict__ Wo, const float* __restrict__ bo,
                  float* __restrict__ out)
{
    __shared__ float As[16][132];
    __shared__ float Bs[16][68];
    int tid = threadIdx.x;
    int tx = tid & 15, ty = tid >> 4;
    int m0 = blockIdx.y * 128, n0 = blockIdx.x * 64;
    int b = m0 / L_;
    int l0 = m0 - b * L_;
    float acc[8][4] = {};

    int mA = tid >> 2, gA = tid & 3;
    int kB = tid >> 4, gB = tid & 15;

    for (int k0 = 0; k0 < 512; k0 += 16) {
        int h = k0 >> 6, dh0 = k0 & 63;
        #pragma unroll
        for (int half = 0; half < 2; half++) {
            int m = half * 64 + mA;
            // splits that wrote partials for this 64-row q-tile
            int nsH = (l0 + half * 64 + 64 + SPLITW - 1) / SPLITW;
            const float* base = g_op + (((size_t)(b*8 + h) * L_ + l0 + m) * 64 + dh0 + gA*4);
            float4 a4 = *(const float4*)(base);
            for (int ss = 1; ss < nsH; ss++) {
                float4 t = *(const float4*)(base + (size_t)ss * (BH_*L_*DH_));
                a4.x += t.x; a4.y += t.y; a4.z += t.z; a4.w += t.w;
            }
            As[gA*4+0][m] = a4.x; As[gA*4+1][m] = a4.y;
            As[gA*4+2][m] = a4.z; As[gA*4+3][m] = a4.w;
        }
        float4 wv = *(const float4*)(Wo + (size_t)(k0 + kB) * 512 + n0 + gB * 4);
        Bs[kB][gB*4+0] = wv.x; Bs[kB][gB*4+1] = wv.y;
        Bs[kB][gB*4+2] = wv.z; Bs[kB][gB*4+3] = wv.w;
        __syncthreads();
        #pragma unroll
        for (int kk = 0; kk < 16; kk++) {
            float a[8], bv[4];
            #pragma unroll
            for (int i = 0; i < 8; i++) a[i] = As[kk][ty * 8 + i];
            #pragma unroll
            for (int j = 0; j < 4; j++) bv[j] = Bs[kk][tx * 4 + j];
            #pragma unroll
            for (int i = 0; i < 8; i++)
                #pragma unroll
                for (int j = 0; j < 4; j++)
                    acc[i][j] += a[i] * bv[j];
        }
        __syncthreads();
    }
    float b0 = bo[n0 + tx*4 + 0], b1 = bo[n0 + tx*4 + 1];
    float b2 = bo[n0 + tx*4 + 2], b3 = bo[n0 + tx*4 + 3];
    #pragma unroll
    for (int i = 0; i < 8; i++) {
        float4 o = make_float4(acc[i][0] + b0, acc[i][1] + b1,
                               acc[i][2] + b2, acc[i][3] + b3);
        *(float4*)(out + (size_t)(m0 + ty*8 + i) * 512 + n0 + tx*4) = o;
    }
}

// ---------------------------------------------------------------------------
extern "C" void kernel_launch(void* const* d_in, const int* in_sizes, int n_in,
                              void* d_out, int out_size)
{
    const float* q  = (const float*)d_in[0];
    const float* k  = (const float*)d_in[1];
    const float* v  = (const float*)d_in[2];
    const float* Wq = (const float*)d_in[4];
    const float* bq = (const float*)d_in[5];
    const float* Wk = (const float*)d_in[6];
    const float* bk = (const float*)d_in[7];
    const float* Wv = (const float*)d_in[8];
    const float* bv = (const float*)d_in[9];
    const float* E  = (const float*)d_in[10];
    const float* Wo = (const float*)d_in[11];
    const float* bo = (const float*)d_in[12];

    float* out_ptr  = (float*)d_out;
    float* attn_ptr = out_ptr + OUT_ELEMS;   // tuple order: (out, attn)

    cudaFuncSetAttribute(scores_kernel,
                         cudaFuncAttributeMaxDynamicSharedMemorySize, SC_SMEM);

    qkv_proj_kernel<<<dim3(8, 30, 3), 256>>>(q, k, v, Wq, Wk, Wv, bq, bk, bv);
    scores_kernel<<<dim3(465, 16), 256, SC_SMEM>>>(E, attn_ptr);
    statcomb_kernel<<<(BH_ * L_ + 255) / 256, 256>>>();
    av_kernel<<<dim3(30, 16, NSPLIT), 256>>>(attn_ptr);
    oproj_kernel<<<dim3(8, 30), 256>>>(Wo, bo, out_ptr);
}

// round 13
// speedup vs baseline: 1.4313x; 1.0152x over previous
#include <cuda_runtime.h>
#include <cuda_bf16.h>
#include <mma.h>
#include <cstdint>
#include <cstddef>

using namespace nvcuda;

#define B_ 2
#define L_ 1920
#define D_ 512
#define H_ 8
#define DH_ 64
#define BH_ (B_*H_)
#define NT_ 30
#define OUT_ELEMS (B_*L_*D_)
#define NSPLIT 4
#define SPLITW 480

// Scratch (device globals; no cudaMalloc allowed)
__device__ float g_qp[B_*L_*D_];
__device__ float g_kp[B_*L_*D_];
__device__ float g_vp[B_*L_*D_];
__device__ float g_op[NSPLIT * BH_*L_*DH_];
__device__ float2 g_stats[BH_*NT_*L_];
__device__ float  g_F[BH_*NT_*L_];
// bf16 hi/lo splits for tensor-core qkv
__device__ __nv_bfloat16 g_ih[3u*3840u*512u];
__device__ __nv_bfloat16 g_il[3u*3840u*512u];
__device__ __nv_bfloat16 g_wh[3u*512u*512u];   // W, [k][n] (original layout)
__device__ __nv_bfloat16 g_wl[3u*512u*512u];

// ---------------------------------------------------------------------------
// Split q/k/v inputs into bf16 hi/lo.
// ---------------------------------------------------------------------------
__global__ __launch_bounds__(256)
void split_in_kernel(const float* __restrict__ q, const float* __restrict__ k,
                     const float* __restrict__ v)
{
    int z = blockIdx.y;
    const float* src = (z == 0) ? q : (z == 1) ? k : v;
    size_t b4 = (size_t)blockIdx.x * 256 + threadIdx.x;   // float4 index
    float4 xv = ((const float4*)src)[b4];
    float xs[4] = {xv.x, xv.y, xv.z, xv.w};
    __nv_bfloat16 hb[4], lb[4];
    #pragma unroll
    for (int j = 0; j < 4; j++) {
        hb[j] = __float2bfloat16(xs[j]);
        lb[j] = __float2bfloat16(xs[j] - __bfloat162float(hb[j]));
    }
    size_t e0 = (size_t)z * (3840u*512u) + b4 * 4;
    __nv_bfloat162* dh = (__nv_bfloat162*)(g_ih + e0);
    __nv_bfloat162* dl = (__nv_bfloat162*)(g_il + e0);
    dh[0] = __halves2bfloat162(hb[0], hb[1]);
    dh[1] = __halves2bfloat162(hb[2], hb[3]);
    dl[0] = __halves2bfloat162(lb[0], lb[1]);
    dl[1] = __halves2bfloat162(lb[2], lb[3]);
}

// ---------------------------------------------------------------------------
// Split weights into bf16 hi/lo (layout preserved: [k][n]).
// ---------------------------------------------------------------------------
__global__ __launch_bounds__(256)
void split_w_kernel(const float* __restrict__ Wq, const float* __restrict__ Wk,
                    const float* __restrict__ Wv)
{
    int z = blockIdx.y;
    const float* W = (z == 0) ? Wq : (z == 1) ? Wk : Wv;
    size_t b4 = (size_t)blockIdx.x * 256 + threadIdx.x;   // float4 index
    float4 xv = ((const float4*)W)[b4];
    float xs[4] = {xv.x, xv.y, xv.z, xv.w};
    __nv_bfloat16 hb[4], lb[4];
    #pragma unroll
    for (int j = 0; j < 4; j++) {
        hb[j] = __float2bfloat16(xs[j]);
        lb[j] = __float2bfloat16(xs[j] - __bfloat162float(hb[j]));
    }
    size_t e0 = (size_t)z * (512u*512u) + b4 * 4;
    __nv_bfloat162* dh = (__nv_bfloat162*)(g_wh + e0);
    __nv_bfloat162* dl = (__nv_bfloat162*)(g_wl + e0);
    dh[0] = __halves2bfloat162(hb[0], hb[1]);
    dh[1] = __halves2bfloat162(hb[2], hb[3]);
    dl[0] = __halves2bfloat162(lb[0], lb[1]);
    dl[1] = __halves2bfloat162(lb[2], lb[3]);
}

// ---------------------------------------------------------------------------
// Tensor-core (WMMA bf16) QKV GEMM: C[128,64] tile = A @ W + bias.
// D = Ah·Bh + Ah·Bl + Al·Bh (fp32 accum); 8 warps, each 32x32 of C.
// ---------------------------------------------------------------------------
#define ASTRIDE 40   // bf16 elems; 80B, multiple of 16B
#define BSTRIDE 72   // bf16 elems; 144B
#define AH_OFF 0
#define AL_OFF 10240
#define BH_OFF 20480
#define BL_OFF 25088
#define STAGE_BYTES 29696
#define CS_BYTES (128*68*4)            // 34816
#define QKV_DSMEM CS_BYTES             // overlay: stage area aliases C area

__global__ __launch_bounds__(256)
void qkv_wmma_kernel(const float* __restrict__ bq, const float* __restrict__ bk,
                     const float* __restrict__ bv)
{
    extern __shared__ char dsm[];
    int tid = threadIdx.x, wid = tid >> 5;
    int z = blockIdx.z, m0 = blockIdx.y * 128, n0 = blockIdx.x * 64;

    const __nv_bfloat16* Ah = g_ih + (size_t)z * (3840u*512u);
    const __nv_bfloat16* Al = g_il + (size_t)z * (3840u*512u);
    const __nv_bfloat16* Bh = g_wh + (size_t)z * (512u*512u);
    const __nv_bfloat16* Bl = g_wl + (size_t)z * (512u*512u);
    float* C = (z == 0) ? g_qp : (z == 1) ? g_kp : g_vp;
    const float* bias = (z == 0) ? bq : (z == 1) ? bk : bv;

    __nv_bfloat16* sAh = (__nv_bfloat16*)(dsm + AH_OFF);
    __nv_bfloat16* sAl = (__nv_bfloat16*)(dsm + AL_OFF);
    __nv_bfloat16* sBh = (__nv_bfloat16*)(dsm + BH_OFF);
    __nv_bfloat16* sBl = (__nv_bfloat16*)(dsm + BL_OFF);

    int wm = wid & 3, wn = wid >> 2;   // warp tile: rows 32*wm, cols 32*wn

    wmma::fragment<wmma::accumulator, 16, 16, 16, float> acc[2][2];
    #pragma unroll
    for (int i = 0; i < 2; i++)
        #pragma unroll
        for (int j = 0; j < 2; j++)
            wmma::fill_fragment(acc[i][j], 0.0f);

    for (int k0 = 0; k0 < 512; k0 += 32) {
        // stage A chunk (128 x 32) hi/lo: 512 uint4 per matrix
        #pragma unroll
        for (int t = 0; t < 2; t++) {
            int u = tid * 2 + t;             // 0..511
            int r = u >> 2, c4 = u & 3;      // uint4 = 8 bf16
            const uint4* sh = (const uint4*)(Ah + (size_t)(m0 + r) * 512 + k0 + c4 * 8);
            const uint4* sl = (const uint4*)(Al + (size_t)(m0 + r) * 512 + k0 + c4 * 8);
            *(uint4*)(sAh + r * ASTRIDE + c4 * 8) = *sh;
            *(uint4*)(sAl + r * ASTRIDE + c4 * 8) = *sl;
        }
        // stage B chunk (32 x 64) hi/lo: 256 uint4 per matrix
        {
            int r = tid >> 3, c4 = tid & 7;
            const uint4* sh = (const uint4*)(Bh + (size_t)(k0 + r) * 512 + n0 + c4 * 8);
            const uint4* sl = (const uint4*)(Bl + (size_t)(k0 + r) * 512 + n0 + c4 * 8);
            *(uint4*)(sBh + r * BSTRIDE + c4 * 8) = *sh;
            *(uint4*)(sBl + r * BSTRIDE + c4 * 8) = *sl;
        }
        __syncthreads();

        #pragma unroll
        for (int kk = 0; kk < 32; kk += 16) {
            wmma::fragment<wmma::matrix_a, 16, 16, 16, __nv_bfloat16, wmma::row_major> ah[2], al[2];
            wmma::fragment<wmma::matrix_b, 16, 16, 16, __nv_bfloat16, wmma::row_major> bh[2], bl[2];
            #pragma unroll
            for (int i = 0; i < 2; i++) {
                wmma::load_matrix_sync(ah[i], sAh + (wm*32 + i*16) * ASTRIDE + kk, ASTRIDE);
                wmma::load_matrix_sync(al[i], sAl + (wm*32 + i*16) * ASTRIDE + kk, ASTRIDE);
            }
            #pragma unroll
            for (int j = 0; j < 2; j++) {
                wmma::load_matrix_sync(bh[j], sBh + kk * BSTRIDE + wn*32 + j*16, BSTRIDE);
                wmma::load_matrix_sync(bl[j], sBl + kk * BSTRIDE + wn*32 + j*16, BSTRIDE);
            }
            #pragma unroll
            for (int i = 0; i < 2; i++)
                #pragma unroll
                for (int j = 0; j < 2; j++) {
                    wmma::mma_sync(acc[i][j], ah[i], bh[j], acc[i][j]);
                    wmma::mma_sync(acc[i][j], ah[i], bl[j], acc[i][j]);
                    wmma::mma_sync(acc[i][j], al[i], bh[j], acc[i][j]);
                }
        }
        __syncthreads();
    }

    // write accumulators to smem C staging (aliases the stage buffers)
    float* Cs = (float*)dsm;     // [128][68]
    #pragma unroll
    for (int i = 0; i < 2; i++)
        #pragma unroll
        for (int j = 0; j < 2; j++)
            wmma::store_matrix_sync(Cs + (size_t)(wm*32 + i*16) * 68 + wn*32 + j*16,
                                    acc[i][j], 68, wmma::mem_row_major);
    __syncthreads();

    // C = Cs + bias -> global
    #pragma unroll
    for (int t = 0; t < 8; t++) {
        int u = tid + t * 256;           // 0..2047 (128 rows x 16 float4)
        int r = u >> 4, c4 = u & 15;
        float4 o = *(float4*)(Cs + (size_t)r * 68 + c4 * 4);
        o.x += bias[n0 + c4*4 + 0]; o.y += bias[n0 + c4*4 + 1];
        o.z += bias[n0 + c4*4 + 2]; o.w += bias[n0 + c4*4 + 3];
        *(float4*)(C + (size_t)(m0 + r) * 512 + n0 + c4 * 4) = o;
    }
}

// ---------------------------------------------------------------------------
// Scores, 64x64 tile, full tile staged once in dynamic smem (verified R10).
// ---------------------------------------------------------------------------
#define QS_OFF 0
#define KS_OFF (64*68)
#define ES_OFF (2*64*68)
#define SC_SMEM ((2*64*68 + 64*132) * 4)

__global__ __launch_bounds__(256)
void scores_kernel(const float* __restrict__ E, float* __restrict__ attn)
{
    extern __shared__ float smf[];
    float* Qs = smf + QS_OFF;
    float* Ks = smf + KS_OFF;
    float* Es = smf + ES_OFF;

    int idx = blockIdx.x;
    int qt = (int)((sqrtf(8.f * idx + 1.f) - 1.f) * 0.5f);
    while ((qt + 1) * (qt + 2) / 2 <= idx) qt++;
    while (qt * (qt + 1) / 2 > idx) qt--;
    int kt = idx - qt * (qt + 1) / 2;

    int bh = blockIdx.y;
    int b = bh >> 3, h = bh & 7;
    int q0 = qt * 64, k0 = kt * 64;

    int tid = threadIdx.x;
    int tx = tid & 15, ty = tid >> 4;

    const float* qbase = g_qp + (size_t)b * L_ * 512 + h * 64;
    const float* kbase = g_kp + (size_t)b * L_ * 512 + h * 64;
    int rbase = k0 - q0 + 1856;

    #pragma unroll
    for (int r = 0; r < 4; r++) {
        int u = tid + r * 256;
        int m = u >> 4, g = u & 15;
        float4 qv = *(const float4*)(qbase + (size_t)(q0 + m) * 512 + g * 4);
        Qs[(g*4+0)*68 + m] = qv.x; Qs[(g*4+1)*68 + m] = qv.y;
        Qs[(g*4+2)*68 + m] = qv.z; Qs[(g*4+3)*68 + m] = qv.w;
        float4 kv = *(const float4*)(kbase + (size_t)(k0 + m) * 512 + g * 4);
        Ks[(g*4+0)*68 + m] = kv.x; Ks[(g*4+1)*68 + m] = kv.y;
        Ks[(g*4+2)*68 + m] = kv.z; Ks[(g*4+3)*68 + m] = kv.w;
    }
    #pragma unroll
    for (int r = 0; r < 8; r++) {
        int u = tid + r * 256;
        if (u < 127 * 16) {
            int ro = u >> 4, g = u & 15;
            int rr = rbase + ro;
            float4 ev = make_float4(0.f, 0.f, 0.f, 0.f);
            if (rr >= 0 && rr < L_)
                ev = *(const float4*)(E + (size_t)(rr + 1) * 512 + h * 64 + g * 4);
            Es[(g*4+0)*132 + ro] = ev.x; Es[(g*4+1)*132 + ro] = ev.y;
            Es[(g*4+2)*132 + ro] = ev.z; Es[(g*4+3)*132 + ro] = ev.w;
        }
    }
    __syncthreads();

    float acc[4][4] = {};
    int ebase = 4 * (tx - ty) + 60;
    #pragma unroll 16
    for (int dd = 0; dd < 64; dd++) {
        float a[4], kv[4], ev[7];
        #pragma unroll
        for (int i = 0; i < 4; i++) a[i] = Qs[dd*68 + ty*4 + i];
        #pragma unroll
        for (int j = 0; j < 4; j++) kv[j] = Ks[dd*68 + tx*4 + j];
        #pragma unroll
        for (int t = 0; t < 7; t++) ev[t] = Es[dd*132 + ebase + t];
        #pragma unroll
        for (int i = 0; i < 4; i++)
            #pragma unroll
            for (int j = 0; j < 4; j++)
                acc[i][j] += a[i] * (kv[j] + ev[j - i + 3]);
    }

    bool diag = (qt == kt);
    float* out = attn + ((size_t)bh * L_ + q0) * L_ + k0;
    #pragma unroll
    for (int i = 0; i < 4; i++) {
        float v[4];
        #pragma unroll
        for (int j = 0; j < 4; j++) v[j] = acc[i][j] * 0.125f;

        int row = ty * 4 + i;
        float m = -1e30f;
        #pragma unroll
        for (int j = 0; j < 4; j++) {
            bool valid = !diag || (tx * 4 + j <= row);
            if (valid) m = fmaxf(m, v[j]);
        }
        #pragma unroll
        for (int off = 8; off > 0; off >>= 1)
            m = fmaxf(m, __shfl_xor_sync(0xffffffffu, m, off, 16));

        float e[4];
        #pragma unroll
        for (int j = 0; j < 4; j++) e[j] = __expf(v[j] - m);
        *(float4*)(out + (size_t)row * L_ + tx*4) =
            make_float4(e[0], e[1], e[2], e[3]);

        float s = 0.f;
        #pragma unroll
        for (int j = 0; j < 4; j++) {
            bool valid = !diag || (tx * 4 + j <= row);
            if (valid) s += e[j];
        }
        #pragma unroll
        for (int off = 8; off > 0; off >>= 1)
            s += __shfl_xor_sync(0xffffffffu, s, off, 16);
        if (tx == 0)
            g_stats[((size_t)bh * NT_ + kt) * L_ + q0 + row] = make_float2(m, s);
    }
}

// ---------------------------------------------------------------------------
__global__ __launch_bounds__(256)
void statcomb_kernel()
{
    int p = blockIdx.x * 256 + threadIdx.x;
    if (p >= BH_ * L_) return;
    int bh = p / L_, q = p - bh * L_;
    int nt = q / 64 + 1;

    const float2* st = g_stats + (size_t)bh * NT_ * L_ + q;
    float M = -1e30f;
    for (int t = 0; t < nt; t++) M = fmaxf(M, st[(size_t)t * L_].x);
    float S = 0.f;
    for (int t = 0; t < nt; t++) {
        float2 v = st[(size_t)t * L_];
        S += v.y * __expf(v.x - M);
    }
    float I = 1.f / S;
    float* F = g_F + (size_t)bh * NT_ * L_ + q;
    for (int t = 0; t < nt; t++)
        F[(size_t)t * L_] = __expf(st[(size_t)t * L_].x - M) * I;
}

// ---------------------------------------------------------------------------
// Fused normalize + AV (split-K) + zerofill. 64-row tiles, prefetch (R10).
// ---------------------------------------------------------------------------
__global__ __launch_bounds__(256)
void av_kernel(float* __restrict__ attn)
{
    int qt = blockIdx.x;
    int bh = blockIdx.y;
    int s  = blockIdx.z;
    int b = bh >> 3, h = bh & 7;
    int q0 = qt * 64;
    int tid = threadIdx.x;

    int kbeg = s * SPLITW;
    int kend = min(q0 + 64, kbeg + SPLITW);

    float* arow = attn + ((size_t)bh * L_ + q0) * L_;

    if (kbeg < kend) {
        __shared__ float As[16][68];
        __shared__ float Bs[16][68];
        int tx = tid & 15, ty = tid >> 4;
        float acc[4][4] = {};

        const float* vbase = g_vp + (size_t)b * L_ * 512 + h * 64;
        const float* Fb = g_F + (size_t)bh * NT_ * L_;
        int mA = tid >> 2, gA = tid & 3;
        int kB = tid >> 4, gB = tid & 15;
        int qrow = q0 + mA;

        float4 xv = *(float4*)(arow + (size_t)mA * L_ + kbeg + gA * 4);
        float4 vv = *(const float4*)(vbase + (size_t)(kbeg + kB) * 512 + gB * 4);
        float Fc = Fb[(size_t)(kbeg >> 6) * L_ + qrow];

        for (int k0 = kbeg; k0 < kend; k0 += 16) {
            int kb = k0 + gA * 4;
            float4 p;
            p.x = (kb + 0 <= qrow) ? xv.x * Fc : 0.f;
            p.y = (kb + 1 <= qrow) ? xv.y * Fc : 0.f;
            p.z = (kb + 2 <= qrow) ? xv.z * Fc : 0.f;
            p.w = (kb + 3 <= qrow) ? xv.w * Fc : 0.f;
            *(float4*)(arow + (size_t)mA * L_ + kb) = p;
            As[gA*4+0][mA] = p.x; As[gA*4+1][mA] = p.y;
            As[gA*4+2][mA] = p.z; As[gA*4+3][mA] = p.w;
            Bs[kB][gB*4+0] = vv.x; Bs[kB][gB*4+1] = vv.y;
            Bs[kB][gB*4+2] = vv.z; Bs[kB][gB*4+3] = vv.w;
            __syncthreads();
            if (k0 + 16 < kend) {
                xv = *(float4*)(arow + (size_t)mA * L_ + k0 + 16 + gA * 4);
                vv = *(const float4*)(vbase + (size_t)(k0 + 16 + kB) * 512 + gB * 4);
                Fc = Fb[(size_t)((k0 + 16) >> 6) * L_ + qrow];
            }
            #pragma unroll
            for (int kk = 0; kk < 16; kk++) {
                float a[4], bv[4];
                #pragma unroll
                for (int i = 0; i < 4; i++) a[i] = As[kk][ty * 4 + i];
                #pragma unroll
                for (int j = 0; j < 4; j++) bv[j] = Bs[kk][tx * 4 + j];
                #pragma unroll
                for (int i = 0; i < 4; i++)
                    #pragma unroll
                    for (int j = 0; j < 4; j++)
                        acc[i][j] += a[i] * bv[j];
            }
            __syncthreads();
        }

        float* op = g_op + (size_t)s * (BH_*L_*DH_) + ((size_t)bh * L_ + q0) * 64;
        #pragma unroll
        for (int i = 0; i < 4; i++) {
            float4 o = make_float4(acc[i][0], acc[i][1], acc[i][2], acc[i][3]);
            *(float4*)(op + (size_t)(ty*4 + i) * 64 + tx*4) = o;
        }
    }

    int zs = max(kbeg, q0 + 64) >> 2;
    int ze = min(kbeg + SPLITW, L_) >> 2;
    if (zs < ze) {
        float4 z = make_float4(0.f, 0.f, 0.f, 0.f);
        int row = tid >> 2;
        float4* rp = (float4*)(arow + (size_t)row * L_);
        for (int c4 = zs + (tid & 3); c4 < ze; c4 += 4) rp[c4] = z;
    }
}

// ---------------------------------------------------------------------------
// oproj. Tile 128x64, micro 8x4, per-64-row-half split count (verified R10).
// ---------------------------------------------------------------------------
__global__ __launch_bounds__(256)
void oproj_kernel(const float* __restrict__ Wo, const float* __restrict__ bo,
                  float* __restrict__ out)
{
    __shared__ float As[16][132];
    __shared__ float Bs[16][68];
    int tid = threadIdx.x;
    int tx = tid & 15, ty = tid >> 4;
    int m0 = blockIdx.y * 128, n0 = blockIdx.x * 64;
    int b = m0 / L_;
    int l0 = m0 - b * L_;
    float acc[8][4] = {};

    int mA = tid >> 2, gA = tid & 3;
    int kB = tid >> 4, gB = tid & 15;

    for (int k0 = 0; k0 < 512; k0 += 16) {
        int h = k0 >> 6, dh0 = k0 & 63;
        #pragma unroll
        for (int half = 0; half < 2; half++) {
            int m = half * 64 + mA;
            int nsH = (l0 + half * 64 + 64 + SPLITW - 1) / SPLITW;
            const float* base = g_op + (((size_t)(b*8 + h) * L_ + l0 + m) * 64 + dh0 + gA*4);
            float4 a4 = *(const float4*)(base);
            for (int ss = 1; ss < nsH; ss++) {
                float4 t = *(const float4*)(base + (size_t)ss * (BH_*L_*DH_));
                a4.x += t.x; a4.y += t.y; a4.z += t.z; a4.w += t.w;
            }
            As[gA*4+0][m] = a4.x; As[gA*4+1][m] = a4.y;
            As[gA*4+2][m] = a4.z; As[gA*4+3][m] = a4.w;
        }
        float4 wv = *(const float4*)(Wo + (size_t)(k0 + kB) * 512 + n0 + gB * 4);
        Bs[kB][gB*4+0] = wv.x; Bs[kB][gB*4+1] = wv.y;
        Bs[kB][gB*4+2] = wv.z; Bs[kB][gB*4+3] = wv.w;
        __syncthreads();
        #pragma unroll
        for (int kk = 0; kk < 16; kk++) {
            float a[8], bv[4];
            #pragma unroll
            for (int i = 0; i < 8; i++) a[i] = As[kk][ty * 8 + i];
            #pragma unroll
            for (int j = 0; j < 4; j++) bv[j] = Bs[kk][tx * 4 + j];
            #pragma unroll
            for (int i = 0; i < 8; i++)
                #pragma unroll
                for (int j = 0; j < 4; j++)
                    acc[i][j] += a[i] * bv[j];
        }
        __syncthreads();
    }
    float b0 = bo[n0 + tx*4 + 0], b1 = bo[n0 + tx*4 + 1];
    float b2 = bo[n0 + tx*4 + 2], b3 = bo[n0 + tx*4 + 3];
    #pragma unroll
    for (int i = 0; i < 8; i++) {
        float4 o = make_float4(acc[i][0] + b0, acc[i][1] + b1,
                               acc[i][2] + b2, acc[i][3] + b3);
        *(float4*)(out + (size_t)(m0 + ty*8 + i) * 512 + n0 + tx*4) = o;
    }
}

// ---------------------------------------------------------------------------
extern "C" void kernel_launch(void* const* d_in, const int* in_sizes, int n_in,
                              void* d_out, int out_size)
{
    const float* q  = (const float*)d_in[0];
    const float* k  = (const float*)d_in[1];
    const float* v  = (const float*)d_in[2];
    const float* Wq = (const float*)d_in[4];
    const float* bq = (const float*)d_in[5];
    const float* Wk = (const float*)d_in[6];
    const float* bk = (const float*)d_in[7];
    const float* Wv = (const float*)d_in[8];
    const float* bv = (const float*)d_in[9];
    const float* E  = (const float*)d_in[10];
    const float* Wo = (const float*)d_in[11];
    const float* bo = (const float*)d_in[12];

    float* out_ptr  = (float*)d_out;
    float* attn_ptr = out_ptr + OUT_ELEMS;   // tuple order: (out, attn)

    cudaFuncSetAttribute(scores_kernel,
                         cudaFuncAttributeMaxDynamicSharedMemorySize, SC_SMEM);
    cudaFuncSetAttribute(qkv_wmma_kernel,
                         cudaFuncAttributeMaxDynamicSharedMemorySize, QKV_DSMEM);

    split_in_kernel<<<dim3(1920, 3), 256>>>(q, k, v);
    split_w_kernel<<<dim3(256, 3), 256>>>(Wq, Wk, Wv);
    qkv_wmma_kernel<<<dim3(8, 30, 3), 256, QKV_DSMEM>>>(bq, bk, bv);
    scores_kernel<<<dim3(465, 16), 256, SC_SMEM>>>(E, attn_ptr);
    statcomb_kernel<<<(BH_ * L_ + 255) / 256, 256>>>();
    av_kernel<<<dim3(30, 16, NSPLIT), 256>>>(attn_ptr);
    oproj_kernel<<<dim3(8, 30), 256>>>(Wo, bo, out_ptr);
}

// round 16
// speedup vs baseline: 1.7575x; 1.2279x over previous
#include <cuda_runtime.h>
#include <cuda_bf16.h>
#include <mma.h>
#include <cstdint>
#include <cstddef>

using namespace nvcuda;

#define B_ 2
#define L_ 1920
#define D_ 512
#define H_ 8
#define DH_ 64
#define BH_ (B_*H_)
#define NT_ 30
#define OUT_ELEMS (B_*L_*D_)
#define NSPLIT 4
#define SPLITW 480

// Scratch (device globals; no cudaMalloc allowed)
__device__ float g_qp[B_*L_*D_];
__device__ float g_kp[B_*L_*D_];
__device__ float g_vp[B_*L_*D_];
__device__ float g_op[NSPLIT * BH_*L_*DH_];
__device__ float g_s[BH_*NT_*L_];          // per (bh,kt,q): tile row sum of exp
__device__ float g_I[BH_*L_];              // per row: 1/sum
// bf16 hi/lo splits
__device__ __nv_bfloat16 g_ih[3u*3840u*512u];
__device__ __nv_bfloat16 g_il[3u*3840u*512u];
__device__ __nv_bfloat16 g_wh[3u*512u*512u];
__device__ __nv_bfloat16 g_wl[3u*512u*512u];
__device__ __nv_bfloat16 g_qph[3840u*512u];   // qp hi/lo (for scores)
__device__ __nv_bfloat16 g_qpl[3840u*512u];
__device__ __nv_bfloat16 g_kph[3840u*512u];
__device__ __nv_bfloat16 g_kpl[3840u*512u];
__device__ __nv_bfloat16 g_eh[1921u*512u];    // E hi/lo
__device__ __nv_bfloat16 g_el[1921u*512u];

// ---------------------------------------------------------------------------
// Split q/k/v inputs into bf16 hi/lo.
// ---------------------------------------------------------------------------
__global__ __launch_bounds__(256)
void split_in_kernel(const float* __restrict__ q, const float* __restrict__ k,
                     const float* __restrict__ v)
{
    int z = blockIdx.y;
    const float* src = (z == 0) ? q : (z == 1) ? k : v;
    size_t b4 = (size_t)blockIdx.x * 256 + threadIdx.x;
    float4 xv = ((const float4*)src)[b4];
    float xs[4] = {xv.x, xv.y, xv.z, xv.w};
    __nv_bfloat16 hb[4], lb[4];
    #pragma unroll
    for (int j = 0; j < 4; j++) {
        hb[j] = __float2bfloat16(xs[j]);
        lb[j] = __float2bfloat16(xs[j] - __bfloat162float(hb[j]));
    }
    size_t e0 = (size_t)z * (3840u*512u) + b4 * 4;
    __nv_bfloat162* dh = (__nv_bfloat162*)(g_ih + e0);
    __nv_bfloat162* dl = (__nv_bfloat162*)(g_il + e0);
    dh[0] = __halves2bfloat162(hb[0], hb[1]);
    dh[1] = __halves2bfloat162(hb[2], hb[3]);
    dl[0] = __halves2bfloat162(lb[0], lb[1]);
    dl[1] = __halves2bfloat162(lb[2], lb[3]);
}

// ---------------------------------------------------------------------------
// Split weights into bf16 hi/lo.
// ---------------------------------------------------------------------------
__global__ __launch_bounds__(256)
void split_w_kernel(const float* __restrict__ Wq, const float* __restrict__ Wk,
                    const float* __restrict__ Wv)
{
    int z = blockIdx.y;
    const float* W = (z == 0) ? Wq : (z == 1) ? Wk : Wv;
    size_t b4 = (size_t)blockIdx.x * 256 + threadIdx.x;
    float4 xv = ((const float4*)W)[b4];
    float xs[4] = {xv.x, xv.y, xv.z, xv.w};
    __nv_bfloat16 hb[4], lb[4];
    #pragma unroll
    for (int j = 0; j < 4; j++) {
        hb[j] = __float2bfloat16(xs[j]);
        lb[j] = __float2bfloat16(xs[j] - __bfloat162float(hb[j]));
    }
    size_t e0 = (size_t)z * (512u*512u) + b4 * 4;
    __nv_bfloat162* dh = (__nv_bfloat162*)(g_wh + e0);
    __nv_bfloat162* dl = (__nv_bfloat162*)(g_wl + e0);
    dh[0] = __halves2bfloat162(hb[0], hb[1]);
    dh[1] = __halves2bfloat162(hb[2], hb[3]);
    dl[0] = __halves2bfloat162(lb[0], lb[1]);
    dl[1] = __halves2bfloat162(lb[2], lb[3]);
}

// ---------------------------------------------------------------------------
// Split E into bf16 hi/lo (1921 x 512).
// ---------------------------------------------------------------------------
__global__ __launch_bounds__(256)
void split_e_kernel(const float* __restrict__ E)
{
    size_t b4 = (size_t)blockIdx.x * 256 + threadIdx.x;
    if (b4 * 4 >= 1921u*512u) return;
    float4 xv = ((const float4*)E)[b4];
    float xs[4] = {xv.x, xv.y, xv.z, xv.w};
    __nv_bfloat16 hb[4], lb[4];
    #pragma unroll
    for (int j = 0; j < 4; j++) {
        hb[j] = __float2bfloat16(xs[j]);
        lb[j] = __float2bfloat16(xs[j] - __bfloat162float(hb[j]));
    }
    __nv_bfloat162* dh = (__nv_bfloat162*)(g_eh + b4 * 4);
    __nv_bfloat162* dl = (__nv_bfloat162*)(g_el + b4 * 4);
    dh[0] = __halves2bfloat162(hb[0], hb[1]);
    dh[1] = __halves2bfloat162(hb[2], hb[3]);
    dl[0] = __halves2bfloat162(lb[0], lb[1]);
    dl[1] = __halves2bfloat162(lb[2], lb[3]);
}

// ---------------------------------------------------------------------------
// WMMA QKV GEMM (verified R13). Also emits bf16 hi/lo of qp/kp.
// ---------------------------------------------------------------------------
#define ASTRIDE 40
#define BSTRIDE 72
#define AH_OFF 0
#define AL_OFF 10240
#define BHI_OFF 20480
#define BLO_OFF 25088
#define QKV_DSMEM (128*68*4)

__global__ __launch_bounds__(256)
void qkv_wmma_kernel(const float* __restrict__ bq, const float* __restrict__ bk,
                     const float* __restrict__ bv)
{
    extern __shared__ char dsm[];
    int tid = threadIdx.x, wid = tid >> 5;
    int z = blockIdx.z, m0 = blockIdx.y * 128, n0 = blockIdx.x * 64;

    const __nv_bfloat16* Ah = g_ih + (size_t)z * (3840u*512u);
    const __nv_bfloat16* Al = g_il + (size_t)z * (3840u*512u);
    const __nv_bfloat16* Bh = g_wh + (size_t)z * (512u*512u);
    const __nv_bfloat16* Bl = g_wl + (size_t)z * (512u*512u);
    float* C = (z == 0) ? g_qp : (z == 1) ? g_kp : g_vp;
    const float* bias = (z == 0) ? bq : (z == 1) ? bk : bv;

    __nv_bfloat16* sAh = (__nv_bfloat16*)(dsm + AH_OFF);
    __nv_bfloat16* sAl = (__nv_bfloat16*)(dsm + AL_OFF);
    __nv_bfloat16* sBh = (__nv_bfloat16*)(dsm + BHI_OFF);
    __nv_bfloat16* sBl = (__nv_bfloat16*)(dsm + BLO_OFF);

    int wm = wid & 3, wn = wid >> 2;

    wmma::fragment<wmma::accumulator, 16, 16, 16, float> acc[2][2];
    #pragma unroll
    for (int i = 0; i < 2; i++)
        #pragma unroll
        for (int j = 0; j < 2; j++)
            wmma::fill_fragment(acc[i][j], 0.0f);

    for (int k0 = 0; k0 < 512; k0 += 32) {
        #pragma unroll
        for (int t = 0; t < 2; t++) {
            int u = tid * 2 + t;
            int r = u >> 2, c4 = u & 3;
            *(uint4*)(sAh + r * ASTRIDE + c4 * 8) =
                *(const uint4*)(Ah + (size_t)(m0 + r) * 512 + k0 + c4 * 8);
            *(uint4*)(sAl + r * ASTRIDE + c4 * 8) =
                *(const uint4*)(Al + (size_t)(m0 + r) * 512 + k0 + c4 * 8);
        }
        {
            int r = tid >> 3, c4 = tid & 7;
            *(uint4*)(sBh + r * BSTRIDE + c4 * 8) =
                *(const uint4*)(Bh + (size_t)(k0 + r) * 512 + n0 + c4 * 8);
            *(uint4*)(sBl + r * BSTRIDE + c4 * 8) =
                *(const uint4*)(Bl + (size_t)(k0 + r) * 512 + n0 + c4 * 8);
        }
        __syncthreads();

        #pragma unroll
        for (int kk = 0; kk < 32; kk += 16) {
            wmma::fragment<wmma::matrix_a, 16, 16, 16, __nv_bfloat16, wmma::row_major> ah[2], al[2];
            wmma::fragment<wmma::matrix_b, 16, 16, 16, __nv_bfloat16, wmma::row_major> bh[2], bl[2];
            #pragma unroll
            for (int i = 0; i < 2; i++) {
                wmma::load_matrix_sync(ah[i], sAh + (wm*32 + i*16) * ASTRIDE + kk, ASTRIDE);
                wmma::load_matrix_sync(al[i], sAl + (wm*32 + i*16) * ASTRIDE + kk, ASTRIDE);
            }
            #pragma unroll
            for (int j = 0; j < 2; j++) {
                wmma::load_matrix_sync(bh[j], sBh + kk * BSTRIDE + wn*32 + j*16, BSTRIDE);
                wmma::load_matrix_sync(bl[j], sBl + kk * BSTRIDE + wn*32 + j*16, BSTRIDE);
            }
            #pragma unroll
            for (int i = 0; i < 2; i++)
                #pragma unroll
                for (int j = 0; j < 2; j++) {
                    wmma::mma_sync(acc[i][j], ah[i], bh[j], acc[i][j]);
                    wmma::mma_sync(acc[i][j], ah[i], bl[j], acc[i][j]);
                    wmma::mma_sync(acc[i][j], al[i], bh[j], acc[i][j]);
                }
        }
        __syncthreads();
    }

    float* Cs = (float*)dsm;
    #pragma unroll
    for (int i = 0; i < 2; i++)
        #pragma unroll
        for (int j = 0; j < 2; j++)
            wmma::store_matrix_sync(Cs + (size_t)(wm*32 + i*16) * 68 + wn*32 + j*16,
                                    acc[i][j], 68, wmma::mem_row_major);
    __syncthreads();

    #pragma unroll
    for (int t = 0; t < 8; t++) {
        int u = tid + t * 256;
        int r = u >> 4, c4 = u & 15;
        float4 o = *(float4*)(Cs + (size_t)r * 68 + c4 * 4);
        o.x += bias[n0 + c4*4 + 0]; o.y += bias[n0 + c4*4 + 1];
        o.z += bias[n0 + c4*4 + 2]; o.w += bias[n0 + c4*4 + 3];
        size_t base = (size_t)(m0 + r) * 512 + n0 + c4 * 4;
        *(float4*)(C + base) = o;
        if (z <= 1) {   // bf16 hi/lo for scores consumption
            __nv_bfloat16* Hh = (z == 0) ? g_qph : g_kph;
            __nv_bfloat16* Hl = (z == 0) ? g_qpl : g_kpl;
            float os[4] = {o.x, o.y, o.z, o.w};
            __nv_bfloat16 hb[4], lb[4];
            #pragma unroll
            for (int j = 0; j < 4; j++) {
                hb[j] = __float2bfloat16(os[j]);
                lb[j] = __float2bfloat16(os[j] - __bfloat162float(hb[j]));
            }
            __nv_bfloat162* dh = (__nv_bfloat162*)(Hh + base);
            __nv_bfloat162* dl = (__nv_bfloat162*)(Hl + base);
            dh[0] = __halves2bfloat162(hb[0], hb[1]);
            dh[1] = __halves2bfloat162(hb[2], hb[3]);
            dl[0] = __halves2bfloat162(lb[0], lb[1]);
            dl[1] = __halves2bfloat162(lb[2], lb[3]);
        }
    }
}

// ---------------------------------------------------------------------------
// WMMA scores: per 64x64 causal tile compute S = Q@K^T (64x64) and
// T = Q@Eband^T (64x128), then ex = exp((S+T_band)*0.125) masked, row sums.
// Band indexing identical to verified scalar kernel (rbase = k0-q0+1856).
// ---------------------------------------------------------------------------
#define SQH 0
#define SQL 9216
#define SKH 18432
#define SKL 27648
#define SEH 36864
#define SEL 55296
#define SCW_SMEM 73728

__global__ __launch_bounds__(256)
void scores_wmma_kernel(float* __restrict__ attn)
{
    extern __shared__ char dsm[];
    __nv_bfloat16* sQh = (__nv_bfloat16*)(dsm + SQH);
    __nv_bfloat16* sQl = (__nv_bfloat16*)(dsm + SQL);
    __nv_bfloat16* sKh = (__nv_bfloat16*)(dsm + SKH);
    __nv_bfloat16* sKl = (__nv_bfloat16*)(dsm + SKL);
    __nv_bfloat16* sEh = (__nv_bfloat16*)(dsm + SEH);
    __nv_bfloat16* sEl = (__nv_bfloat16*)(dsm + SEL);
    float* SO = (float*)dsm;            // overlay after GEMM: [64][68]
    float* TO = (float*)dsm + 64*68;    // [64][132]

    int idx = blockIdx.x;
    int qt = (int)((sqrtf(8.f * idx + 1.f) - 1.f) * 0.5f);
    while ((qt + 1) * (qt + 2) / 2 <= idx) qt++;
    while (qt * (qt + 1) / 2 > idx) qt--;
    int kt = idx - qt * (qt + 1) / 2;

    int bh = blockIdx.y;
    int b = bh >> 3, h = bh & 7;
    int q0 = qt * 64, k0 = kt * 64;
    int rbase = k0 - q0 + 1856;

    int tid = threadIdx.x;
    int tx = tid & 15, ty = tid >> 4, wid = tid >> 5;

    // stage Q/K hi+lo (64 rows x 8 uint4 each)
    #pragma unroll
    for (int r = 0; r < 2; r++) {
        int u = tid + r * 256;
        int row = u >> 3, c8 = (u & 7) * 8;
        size_t qoff = ((size_t)b * L_ + q0 + row) * 512 + h * 64 + c8;
        size_t koff = ((size_t)b * L_ + k0 + row) * 512 + h * 64 + c8;
        *(uint4*)(sQh + row * 72 + c8) = *(const uint4*)(g_qph + qoff);
        *(uint4*)(sQl + row * 72 + c8) = *(const uint4*)(g_qpl + qoff);
        *(uint4*)(sKh + row * 72 + c8) = *(const uint4*)(g_kph + koff);
        *(uint4*)(sKl + row * 72 + c8) = *(const uint4*)(g_kpl + koff);
    }
    // stage E band hi+lo (128 rows x 8 uint4; invalid rows zero)
    uint4 z4 = make_uint4(0, 0, 0, 0);
    #pragma unroll
    for (int r = 0; r < 4; r++) {
        int u = tid + r * 256;
        int row = u >> 3, c8 = (u & 7) * 8;
        int rr = rbase + row;
        bool valid = (row < 127) && (rr >= 0) && (rr < L_);
        size_t eoff = (size_t)(rr + 1) * 512 + h * 64 + c8;
        *(uint4*)(sEh + row * 72 + c8) = valid ? *(const uint4*)(g_eh + eoff) : z4;
        *(uint4*)(sEl + row * 72 + c8) = valid ? *(const uint4*)(g_el + eoff) : z4;
    }
    __syncthreads();

    // GEMM: combined columns [S(4 tiles) | T(8 tiles)] = 12 col-tiles
    int ib = wid & 3, half = wid >> 2;
    wmma::fragment<wmma::accumulator, 16, 16, 16, float> acc[6];
    #pragma unroll
    for (int t = 0; t < 6; t++) wmma::fill_fragment(acc[t], 0.0f);

    #pragma unroll
    for (int kk = 0; kk < 4; kk++) {
        wmma::fragment<wmma::matrix_a, 16, 16, 16, __nv_bfloat16, wmma::row_major> ah, al;
        wmma::load_matrix_sync(ah, sQh + (ib*16) * 72 + kk*16, 72);
        wmma::load_matrix_sync(al, sQl + (ib*16) * 72 + kk*16, 72);
        #pragma unroll
        for (int t = 0; t < 6; t++) {
            int jb = half * 6 + t;
            const __nv_bfloat16 *ph, *pl;
            if (jb < 4) { ph = sKh + (jb*16) * 72 + kk*16; pl = sKl + (jb*16) * 72 + kk*16; }
            else        { ph = sEh + ((jb-4)*16) * 72 + kk*16; pl = sEl + ((jb-4)*16) * 72 + kk*16; }
            wmma::fragment<wmma::matrix_b, 16, 16, 16, __nv_bfloat16, wmma::col_major> bh, bl;
            wmma::load_matrix_sync(bh, ph, 72);
            wmma::load_matrix_sync(bl, pl, 72);
            wmma::mma_sync(acc[t], ah, bh, acc[t]);
            wmma::mma_sync(acc[t], ah, bl, acc[t]);
            wmma::mma_sync(acc[t], al, bh, acc[t]);
        }
    }
    __syncthreads();   // staging reads done before overlay

    #pragma unroll
    for (int t = 0; t < 6; t++) {
        int jb = half * 6 + t;
        if (jb < 4)
            wmma::store_matrix_sync(SO + (size_t)(ib*16) * 68 + jb*16, acc[t], 68,
                                    wmma::mem_row_major);
        else
            wmma::store_matrix_sync(TO + (size_t)(ib*16) * 132 + (jb-4)*16, acc[t], 132,
                                    wmma::mem_row_major);
    }
    __syncthreads();

    // epilogue: ex = exp((S + T_band)/8), diag-masked; row sums (16-lane)
    bool diag = (qt == kt);
    float* out = attn + ((size_t)bh * L_ + q0) * L_ + k0;
    #pragma unroll
    for (int i = 0; i < 4; i++) {
        int row = ty * 4 + i;
        float e4[4];
        #pragma unroll
        for (int j = 0; j < 4; j++) {
            int col = tx * 4 + j;
            float v = (SO[(size_t)row * 68 + col]
                     + TO[(size_t)row * 132 + col - row + 63]) * 0.125f;
            e4[j] = (diag && col > row) ? 0.f : __expf(v);
        }
        *(float4*)(out + (size_t)row * L_ + tx*4) =
            make_float4(e4[0], e4[1], e4[2], e4[3]);
        float s = e4[0] + e4[1] + e4[2] + e4[3];
        #pragma unroll
        for (int off = 8; off > 0; off >>= 1)
            s += __shfl_xor_sync(0xffffffffu, s, off, 16);
        if (tx == 0)
            g_s[((size_t)bh * NT_ + kt) * L_ + q0 + row] = s;
    }
}

// ---------------------------------------------------------------------------
// Combine per-tile sums into per-row 1/sum.
// ---------------------------------------------------------------------------
__global__ __launch_bounds__(256)
void statcomb_kernel()
{
    int p = blockIdx.x * 256 + threadIdx.x;
    if (p >= BH_ * L_) return;
    int bh = p / L_, q = p - bh * L_;
    int nt = q / 64 + 1;

    const float* st = g_s + (size_t)bh * NT_ * L_ + q;
    float S = 0.f;
    for (int t = 0; t < nt; t++) S += st[(size_t)t * L_];
    g_I[p] = 1.f / S;
}

// ---------------------------------------------------------------------------
// Fused normalize + AV (split-K) + zerofill. 64-row tiles, prefetch (R10).
// p = ex * I_row (single per-row scale).
// ---------------------------------------------------------------------------
__global__ __launch_bounds__(256)
void av_kernel(float* __restrict__ attn)
{
    int qt = blockIdx.x;
    int bh = blockIdx.y;
    int s  = blockIdx.z;
    int b = bh >> 3, h = bh & 7;
    int q0 = qt * 64;
    int tid = threadIdx.x;

    int kbeg = s * SPLITW;
    int kend = min(q0 + 64, kbeg + SPLITW);

    float* arow = attn + ((size_t)bh * L_ + q0) * L_;

    if (kbeg < kend) {
        __shared__ float As[16][68];
        __shared__ float Bs[16][68];
        int tx = tid & 15, ty = tid >> 4;
        float acc[4][4] = {};

        const float* vbase = g_vp + (size_t)b * L_ * 512 + h * 64;
        int mA = tid >> 2, gA = tid & 3;
        int kB = tid >> 4, gB = tid & 15;
        int qrow = q0 + mA;
        float Iv = g_I[(size_t)bh * L_ + qrow];

        float4 xv = *(float4*)(arow + (size_t)mA * L_ + kbeg + gA * 4);
        float4 vv = *(const float4*)(vbase + (size_t)(kbeg + kB) * 512 + gB * 4);

        for (int k0 = kbeg; k0 < kend; k0 += 16) {
            int kb = k0 + gA * 4;
            float4 p;
            p.x = (kb + 0 <= qrow) ? xv.x * Iv : 0.f;
            p.y = (kb + 1 <= qrow) ? xv.y * Iv : 0.f;
            p.z = (kb + 2 <= qrow) ? xv.z * Iv : 0.f;
            p.w = (kb + 3 <= qrow) ? xv.w * Iv : 0.f;
            *(float4*)(arow + (size_t)mA * L_ + kb) = p;
            As[gA*4+0][mA] = p.x; As[gA*4+1][mA] = p.y;
            As[gA*4+2][mA] = p.z; As[gA*4+3][mA] = p.w;
            Bs[kB][gB*4+0] = vv.x; Bs[kB][gB*4+1] = vv.y;
            Bs[kB][gB*4+2] = vv.z; Bs[kB][gB*4+3] = vv.w;
            __syncthreads();
            if (k0 + 16 < kend) {
                xv = *(float4*)(arow + (size_t)mA * L_ + k0 + 16 + gA * 4);
                vv = *(const float4*)(vbase + (size_t)(k0 + 16 + kB) * 512 + gB * 4);
            }
            #pragma unroll
            for (int kk = 0; kk < 16; kk++) {
                float a[4], bv[4];
                #pragma unroll
                for (int i = 0; i < 4; i++) a[i] = As[kk][ty * 4 + i];
                #pragma unroll
                for (int j = 0; j < 4; j++) bv[j] = Bs[kk][tx * 4 + j];
                #pragma unroll
                for (int i = 0; i < 4; i++)
                    #pragma unroll
                    for (int j = 0; j < 4; j++)
                        acc[i][j] += a[i] * bv[j];
            }
            __syncthreads();
        }

        float* op = g_op + (size_t)s * (BH_*L_*DH_) + ((size_t)bh * L_ + q0) * 64;
        #pragma unroll
        for (int i = 0; i < 4; i++) {
            float4 o = make_float4(acc[i][0], acc[i][1], acc[i][2], acc[i][3]);
            *(float4*)(op + (size_t)(ty*4 + i) * 64 + tx*4) = o;
        }
    }

    int zs = max(kbeg, q0 + 64) >> 2;
    int ze = min(kbeg + SPLITW, L_) >> 2;
    if (zs < ze) {
        float4 z = make_float4(0.f, 0.f, 0.f, 0.f);
        int row = tid >> 2;
        float4* rp = (float4*)(arow + (size_t)row * L_);
        for (int c4 = zs + (tid & 3); c4 < ze; c4 += 4) rp[c4] = z;
    }
}

// ---------------------------------------------------------------------------
// oproj. Tile 128x64, micro 8x4, per-64-row-half split count (verified R10).
// ---------------------------------------------------------------------------
__global__ __launch_bounds__(256)
void oproj_kernel(const float* __restrict__ Wo, const float* __restrict__ bo,
                  float* __restrict__ out)
{
    __shared__ float As[16][132];
    __shared__ float Bs[16][68];
    int tid = threadIdx.x;
    int tx = tid & 15, ty = tid >> 4;
    int m0 = blockIdx.y * 128, n0 = blockIdx.x * 64;
    int b = m0 / L_;
    int l0 = m0 - b * L_;
    float acc[8][4] = {};

    int mA = tid >> 2, gA = tid & 3;
    int kB = tid >> 4, gB = tid & 15;

    for (int k0 = 0; k0 < 512; k0 += 16) {
        int h = k0 >> 6, dh0 = k0 & 63;
        #pragma unroll
        for (int half = 0; half < 2; half++) {
            int m = half * 64 + mA;
            int nsH = (l0 + half * 64 + 64 + SPLITW - 1) / SPLITW;
            const float* base = g_op + (((size_t)(b*8 + h) * L_ + l0 + m) * 64 + dh0 + gA*4);
            float4 a4 = *(const float4*)(base);
            for (int ss = 1; ss < nsH; ss++) {
                float4 t = *(const float4*)(base + (size_t)ss * (BH_*L_*DH_));
                a4.x += t.x; a4.y += t.y; a4.z += t.z; a4.w += t.w;
            }
            As[gA*4+0][m] = a4.x; As[gA*4+1][m] = a4.y;
            As[gA*4+2][m] = a4.z; As[gA*4+3][m] = a4.w;
        }
        float4 wv = *(const float4*)(Wo + (size_t)(k0 + kB) * 512 + n0 + gB * 4);
        Bs[kB][gB*4+0] = wv.x; Bs[kB][gB*4+1] = wv.y;
        Bs[kB][gB*4+2] = wv.z; Bs[kB][gB*4+3] = wv.w;
        __syncthreads();
        #pragma unroll
        for (int kk = 0; kk < 16; kk++) {
            float a[8], bv[4];
            #pragma unroll
            for (int i = 0; i < 8; i++) a[i] = As[kk][ty * 8 + i];
            #pragma unroll
            for (int j = 0; j < 4; j++) bv[j] = Bs[kk][tx * 4 + j];
            #pragma unroll
            for (int i = 0; i < 8; i++)
                #pragma unroll
                for (int j = 0; j < 4; j++)
                    acc[i][j] += a[i] * bv[j];
        }
        __syncthreads();
    }
    float b0 = bo[n0 + tx*4 + 0], b1 = bo[n0 + tx*4 + 1];
    float b2 = bo[n0 + tx*4 + 2], b3 = bo[n0 + tx*4 + 3];
    #pragma unroll
    for (int i = 0; i < 8; i++) {
        float4 o = make_float4(acc[i][0] + b0, acc[i][1] + b1,
                               acc[i][2] + b2, acc[i][3] + b3);
        *(float4*)(out + (size_t)(m0 + ty*8 + i) * 512 + n0 + tx*4) = o;
    }
}

// ---------------------------------------------------------------------------
extern "C" void kernel_launch(void* const* d_in, const int* in_sizes, int n_in,
                              void* d_out, int out_size)
{
    const float* q  = (const float*)d_in[0];
    const float* k  = (const float*)d_in[1];
    const float* v  = (const float*)d_in[2];
    const float* Wq = (const float*)d_in[4];
    const float* bq = (const float*)d_in[5];
    const float* Wk = (const float*)d_in[6];
    const float* bk = (const float*)d_in[7];
    const float* Wv = (const float*)d_in[8];
    const float* bv = (const float*)d_in[9];
    const float* E  = (const float*)d_in[10];
    const float* Wo = (const float*)d_in[11];
    const float* bo = (const float*)d_in[12];

    float* out_ptr  = (float*)d_out;
    float* attn_ptr = out_ptr + OUT_ELEMS;   // tuple order: (out, attn)

    cudaFuncSetAttribute(qkv_wmma_kernel,
                         cudaFuncAttributeMaxDynamicSharedMemorySize, QKV_DSMEM);
    cudaFuncSetAttribute(scores_wmma_kernel,
                         cudaFuncAttributeMaxDynamicSharedMemorySize, SCW_SMEM);

    split_in_kernel<<<dim3(1920, 3), 256>>>(q, k, v);
    split_w_kernel<<<dim3(256, 3), 256>>>(Wq, Wk, Wv);
    split_e_kernel<<<961, 256>>>(E);
    qkv_wmma_kernel<<<dim3(8, 30, 3), 256, QKV_DSMEM>>>(bq, bk, bv);
    scores_wmma_kernel<<<dim3(465, 16), 256, SCW_SMEM>>>(attn_ptr);
    statcomb_kernel<<<(BH_ * L_ + 255) / 256, 256>>>();
    av_kernel<<<dim3(30, 16, NSPLIT), 256>>>(attn_ptr);
    oproj_kernel<<<dim3(8, 30), 256>>>(Wo, bo, out_ptr);
}